// round 5
// baseline (speedup 1.0000x reference)
#include <cuda_runtime.h>
#include <cstdint>

#define NTOK 8192
#define CDIM 1024
#define DDIM 64
#define BM 64
#define BN 128
#define CHUNKS (NTOK / BN)

// scratch (allocation-free)
__device__ float g_q[NTOK * DDIM];
__device__ float g_k[NTOK * DDIM];
__device__ float g_v[NTOK * DDIM];

// m16n8k8 tf32 HMMA (base-target instruction)
__device__ __forceinline__ void mma_tf32(float* c, const uint32_t* a,
                                         uint32_t b0, uint32_t b1) {
    asm volatile(
        "mma.sync.aligned.m16n8k8.row.col.f32.tf32.tf32.f32 "
        "{%0,%1,%2,%3}, {%4,%5,%6,%7}, {%8,%9}, {%0,%1,%2,%3};"
        : "+f"(c[0]), "+f"(c[1]), "+f"(c[2]), "+f"(c[3])
        : "r"(a[0]), "r"(a[1]), "r"(a[2]), "r"(a[3]), "r"(b0), "r"(b1));
}
__device__ __forceinline__ float tf32r(float v) {
    uint32_t u;
    asm("cvt.rna.tf32.f32 %0, %1;" : "=r"(u) : "f"(v));
    return __uint_as_float(u);
}

// ---------------------------------------------------------------------------
// Kernel 1: QKV projection on tf32 MMA, 2-term x-split (unchanged from R4)
// ---------------------------------------------------------------------------
#define QP 36
__global__ __launch_bounds__(256, 1) void qkv_mma(
    const float* __restrict__ x,
    const float* __restrict__ Wq, const float* __restrict__ bq,
    const float* __restrict__ Wk, const float* __restrict__ bk,
    const float* __restrict__ Wv, const float* __restrict__ bv)
{
    __shared__ float xh[64 * QP];
    __shared__ float xl[64 * QP];
    __shared__ float ws[192 * QP];

    const int tid  = threadIdx.x;
    const int warp = tid >> 5;
    const int lane = tid & 31;
    const int g    = lane >> 2;
    const int t4   = lane & 3;
    const int xg   = g & 4;
    const int wm   = warp & 3;
    const int nh   = warp >> 2;
    const int row0 = blockIdx.x * 64;

    const int xr_r[2]  = { (0 * 256 + tid) >> 3, (1 * 256 + tid) >> 3 };
    const int xr_c4    = tid & 7;
    const float* xptr[2];
    float* xsh[2];
    float* xsl[2];
#pragma unroll
    for (int i = 0; i < 2; i++) {
        xptr[i] = x + (size_t)(row0 + xr_r[i]) * CDIM + xr_c4 * 4;
        int sc = (xr_c4 * 4) ^ (xr_r[i] & 4);
        xsh[i] = xh + xr_r[i] * QP + sc;
        xsl[i] = xl + xr_r[i] * QP + sc;
    }
    const float* wptr[6];
    float* wss[6];
#pragma unroll
    for (int i = 0; i < 6; i++) {
        int idx = i * 256 + tid;
        int j = idx >> 3, c4 = idx & 7;
        const float* Wp = (j < 64) ? Wq : ((j < 128) ? Wk : Wv);
        wptr[i] = Wp + (size_t)(j & 63) * CDIM + c4 * 4;
        wss[i]  = ws + j * QP + ((c4 * 4) ^ (j & 4));
    }

    float4 xreg[2], wreg[6];
#pragma unroll
    for (int i = 0; i < 2; i++) xreg[i] = *(const float4*)(xptr[i]);
#pragma unroll
    for (int i = 0; i < 6; i++) wreg[i] = *(const float4*)(wptr[i]);

    float oacc[12][4];
#pragma unroll
    for (int n = 0; n < 12; n++)
#pragma unroll
        for (int j = 0; j < 4; j++) oacc[n][j] = 0.f;

    for (int kc = 0; kc < 32; kc++) {
        __syncthreads();
#pragma unroll
        for (int i = 0; i < 2; i++) {
            float4 h, l;
            h.x = tf32r(xreg[i].x); l.x = tf32r(xreg[i].x - h.x);
            h.y = tf32r(xreg[i].y); l.y = tf32r(xreg[i].y - h.y);
            h.z = tf32r(xreg[i].z); l.z = tf32r(xreg[i].z - h.z);
            h.w = tf32r(xreg[i].w); l.w = tf32r(xreg[i].w - h.w);
            *(float4*)(xsh[i]) = h;
            *(float4*)(xsl[i]) = l;
        }
#pragma unroll
        for (int i = 0; i < 6; i++) {
            float4 w4 = wreg[i];
            w4.x = tf32r(w4.x); w4.y = tf32r(w4.y);
            w4.z = tf32r(w4.z); w4.w = tf32r(w4.w);
            *(float4*)(wss[i]) = w4;
        }
        __syncthreads();

        if (kc < 31) {
#pragma unroll
            for (int i = 0; i < 2; i++)
                xreg[i] = *(const float4*)(xptr[i] + (kc + 1) * 32);
#pragma unroll
            for (int i = 0; i < 6; i++)
                wreg[i] = *(const float4*)(wptr[i] + (kc + 1) * 32);
        }

        const float* xhr0 = xh + (wm * 16 + g) * QP;
        const float* xhr1 = xh + (wm * 16 + g + 8) * QP;
        const float* xlr0 = xl + (wm * 16 + g) * QP;
        const float* xlr1 = xl + (wm * 16 + g + 8) * QP;
#pragma unroll
        for (int kk = 0; kk < 4; kk++) {
            int c0 = (8 * kk + t4) ^ xg;
            int c1 = (8 * kk + t4 + 4) ^ xg;
            uint32_t ah[4], al[4];
            ah[0] = __float_as_uint(xhr0[c0]);
            ah[1] = __float_as_uint(xhr1[c0]);
            ah[2] = __float_as_uint(xhr0[c1]);
            ah[3] = __float_as_uint(xhr1[c1]);
            al[0] = __float_as_uint(xlr0[c0]);
            al[1] = __float_as_uint(xlr1[c0]);
            al[2] = __float_as_uint(xlr0[c1]);
            al[3] = __float_as_uint(xlr1[c1]);
#pragma unroll
            for (int n = 0; n < 12; n++) {
                const float* wb = ws + (nh * 96 + 8 * n + g) * QP;
                uint32_t b0 = __float_as_uint(wb[c0]);
                uint32_t b1 = __float_as_uint(wb[c1]);
                mma_tf32(oacc[n], ah, b0, b1);
                mma_tf32(oacc[n], al, b0, b1);
            }
        }
    }

    const int r0 = row0 + wm * 16 + g;
#pragma unroll
    for (int n = 0; n < 12; n++) {
        int cb = nh * 96 + 8 * n + 2 * t4;
        float* dst;
        int col;
        const float* bp;
        if (cb < 64)       { dst = g_q; col = cb;       bp = bq; }
        else if (cb < 128) { dst = g_k; col = cb - 64;  bp = bk; }
        else               { dst = g_v; col = cb - 128; bp = bv; }
        float2 bias = *(const float2*)(bp + col);
        *(float2*)(dst + (size_t)r0 * DDIM + col) =
            make_float2(oacc[n][0] + bias.x, oacc[n][1] + bias.y);
        *(float2*)(dst + (size_t)(r0 + 8) * DDIM + col) =
            make_float2(oacc[n][2] + bias.x, oacc[n][3] + bias.y);
    }
}

// ---------------------------------------------------------------------------
// Kernel 2: flash attention, BM=64, no split, register-prefetched staging,
// kk-outer S loop (8 independent accumulator chains), fused tiled output.
// grid 128, 256 thr = 4 m-warps x 2 col-halves.
// ---------------------------------------------------------------------------
#define KPITCH 72
#define PPITCH 136
#define YP 68
#define SM_K 0
#define SM_V (128 * KPITCH)
#define SM_P (2 * 128 * KPITCH)
#define SM_L (SM_P + 64 * PPITCH)
#define FLASH_SMEM_BYTES ((SM_L + 128) * 4)

__global__ __launch_bounds__(256, 1) void flash_mma(float* __restrict__ out)
{
    extern __shared__ float sm[];
    float* Ks = sm + SM_K;
    float* Vs = sm + SM_V;
    float* Ps = sm + SM_P;
    float* lh = sm + SM_L;     // [2][64]
    float* Qs = Ks;            // Q staged in K region before the loop
    float* ys = sm;            // epilogue staging reuses K region

    const int tid  = threadIdx.x;
    const int warp = tid >> 5;
    const int lane = tid & 31;
    const int g    = lane >> 2;
    const int t4   = lane & 3;
    const int xg   = g & 4;
    const int wm   = warp & 3;       // m-tile (16 rows)
    const int nh   = warp >> 2;      // column half
    const int wr0  = wm * 16;
    const int row0 = blockIdx.x * BM;

    // staging coordinates (K and V share the pattern)
    const int st_r  = tid >> 1;           // with i-loop: r = (i*256+tid)>>4
    (void)st_r;

    // stage Q (64 x 64) into Ks region
#pragma unroll
    for (int i = 0; i < 4; i++) {
        int idx = i * 256 + tid;
        int r = idx >> 4, c4 = idx & 15;
        float4 v = *(const float4*)(g_q + (size_t)(row0 + r) * DDIM + c4 * 4);
        *(float4*)(Qs + r * KPITCH + ((c4 * 4) ^ (r & 4))) = v;
    }
    __syncthreads();

    // preload Q A-fragments
    uint32_t aQ[8][4];
    {
        const float* qr0 = Qs + (wr0 + g) * KPITCH;
        const float* qr1 = Qs + (wr0 + g + 8) * KPITCH;
#pragma unroll
        for (int kk = 0; kk < 8; kk++) {
            int c0 = (8 * kk + t4) ^ xg;
            int c1 = (8 * kk + t4 + 4) ^ xg;
            aQ[kk][0] = __float_as_uint(qr0[c0]);
            aQ[kk][1] = __float_as_uint(qr1[c0]);
            aQ[kk][2] = __float_as_uint(qr0[c1]);
            aQ[kk][3] = __float_as_uint(qr1[c1]);
        }
    }

    // prefetch chunk 0 into registers
    float4 kreg[8], vreg[8];
#pragma unroll
    for (int i = 0; i < 8; i++) {
        int idx = i * 256 + tid;
        int r = idx >> 4, c4 = idx & 15;
        kreg[i] = *(const float4*)(g_k + (size_t)r * DDIM + c4 * 4);
        vreg[i] = *(const float4*)(g_v + (size_t)r * DDIM + c4 * 4);
    }

    float oacc[4][4];
#pragma unroll
    for (int n = 0; n < 4; n++)
#pragma unroll
        for (int j = 0; j < 4; j++) oacc[n][j] = 0.f;
    float l0 = 0.f, l1 = 0.f;

    float* pr0 = Ps + (wr0 + g) * PPITCH;
    float* pr1 = Ps + (wr0 + g + 8) * PPITCH;

    for (int ch = 0; ch < CHUNKS; ch++) {
        __syncthreads();   // prev chunk fully consumed (and aQ loads done)

        // store prefetched K/V into swizzled smem
#pragma unroll
        for (int i = 0; i < 8; i++) {
            int idx = i * 256 + tid;
            int r = idx >> 4, c4 = idx & 15;
            int sc = (c4 * 4) ^ (r & 4);
            *(float4*)(Ks + r * KPITCH + sc) = kreg[i];
            *(float4*)(Vs + r * KPITCH + sc) = vreg[i];
        }
        __syncthreads();

        // prefetch next chunk (overlaps with all compute below)
        if (ch < CHUNKS - 1) {
            const size_t nb = (size_t)(ch + 1) * BN;
#pragma unroll
            for (int i = 0; i < 8; i++) {
                int idx = i * 256 + tid;
                int r = idx >> 4, c4 = idx & 15;
                kreg[i] = *(const float4*)(g_k + (nb + r) * DDIM + c4 * 4);
                vreg[i] = *(const float4*)(g_v + (nb + r) * DDIM + c4 * 4);
            }
        }

        // S = Q K^T for this warp's 16 rows x 64-col half.
        // kk outer, n inner -> 8 independent accumulator chains.
        float sacc[8][4];
#pragma unroll
        for (int n = 0; n < 8; n++)
#pragma unroll
            for (int j = 0; j < 4; j++) sacc[n][j] = 0.f;
#pragma unroll
        for (int kk = 0; kk < 8; kk++) {
            int c0 = (8 * kk + t4) ^ xg;
            int c1 = (8 * kk + t4 + 4) ^ xg;
#pragma unroll
            for (int n = 0; n < 8; n++) {
                const float* kb = Ks + (8 * (nh * 8 + n) + g) * KPITCH;
                uint32_t b0 = __float_as_uint(kb[c0]);
                uint32_t b1 = __float_as_uint(kb[c1]);
                mma_tf32(sacc[n], aQ[kk], b0, b1);
            }
        }

        // exp + P store + l accumulation
#pragma unroll
        for (int n = 0; n < 8; n++) {
            float p0 = __expf(sacc[n][0] * 0.03125f);
            float p1 = __expf(sacc[n][1] * 0.03125f);
            float p2 = __expf(sacc[n][2] * 0.03125f);
            float p3 = __expf(sacc[n][3] * 0.03125f);
            l0 += p0 + p1;
            l1 += p2 + p3;
            int pc = (8 * (nh * 8 + n) + 2 * t4) ^ xg;
            *(float2*)(pr0 + pc) = make_float2(p0, p1);
            *(float2*)(pr1 + pc) = make_float2(p2, p3);
        }
        __syncthreads();   // both col-halves of P complete

        // O += P @ V  (n inner: 4 independent chains)
#pragma unroll
        for (int k2 = 0; k2 < 16; k2++) {
            uint32_t aP[4];
            int c0 = (8 * k2 + t4) ^ xg;
            int c1 = (8 * k2 + t4 + 4) ^ xg;
            aP[0] = __float_as_uint(pr0[c0]);
            aP[1] = __float_as_uint(pr1[c0]);
            aP[2] = __float_as_uint(pr0[c1]);
            aP[3] = __float_as_uint(pr1[c1]);
            const float* vb0 = Vs + (8 * k2 + t4) * KPITCH;
            const float* vb1 = Vs + (8 * k2 + t4 + 4) * KPITCH;
#pragma unroll
            for (int n = 0; n < 4; n++) {
                int col = 32 * nh + 8 * n + g;
                uint32_t b0 = __float_as_uint(vb0[col]);
                uint32_t b1 = __float_as_uint(vb1[col ^ 4]);
                mma_tf32(oacc[n], aP, b0, b1);
            }
        }
    }

    // reduce l over the t4 quad, publish per-half row sums
    l0 += __shfl_xor_sync(0xffffffffu, l0, 1);
    l0 += __shfl_xor_sync(0xffffffffu, l0, 2);
    l1 += __shfl_xor_sync(0xffffffffu, l1, 1);
    l1 += __shfl_xor_sync(0xffffffffu, l1, 2);
    __syncthreads();       // all PV reads done before lh/ys overwrite smem
    if (t4 == 0) {
        lh[nh * 64 + wr0 + g]     = l0;
        lh[nh * 64 + wr0 + g + 8] = l1;
    }
    __syncthreads();

    // scale by 1/l and stage y (64 x 64) into smem
    {
        float inv0 = 1.f / (lh[wr0 + g]     + lh[64 + wr0 + g]);
        float inv1 = 1.f / (lh[wr0 + g + 8] + lh[64 + wr0 + g + 8]);
#pragma unroll
        for (int n = 0; n < 4; n++) {
            int col = 32 * nh + 8 * n + 2 * t4;
            *(float2*)(ys + (wr0 + g) * YP + col) =
                make_float2(oacc[n][0] * inv0, oacc[n][1] * inv0);
            *(float2*)(ys + (wr0 + g + 8) * YP + col) =
                make_float2(oacc[n][2] * inv1, oacc[n][3] * inv1);
        }
    }
    __syncthreads();

    // coalesced 16x-tiled output write
#pragma unroll 4
    for (int i = 0; i < 64; i++) {
        int idx = i * 256 + tid;           // float4 slot, 0..16383
        int row = idx >> 8;                // 64 rows, 256 f4 per row
        int c4i = idx & 255;
        float4 v = *(const float4*)(ys + row * YP + (c4i & 15) * 4);
        *(float4*)(out + (size_t)(row0 + row) * 1024 + c4i * 4) = v;
    }
}

// ---------------------------------------------------------------------------
extern "C" void kernel_launch(void* const* d_in, const int* in_sizes, int n_in,
                              void* d_out, int out_size)
{
    const float* x  = (const float*)d_in[0];
    const float* Wq = (const float*)d_in[1];
    const float* bq = (const float*)d_in[2];
    const float* Wk = (const float*)d_in[3];
    const float* bk = (const float*)d_in[4];
    const float* Wv = (const float*)d_in[5];
    const float* bv = (const float*)d_in[6];
    float* out = (float*)d_out;

    qkv_mma<<<128, 256>>>(x, Wq, bq, Wk, bk, Wv, bv);

    cudaFuncSetAttribute(flash_mma, cudaFuncAttributeMaxDynamicSharedMemorySize,
                         FLASH_SMEM_BYTES);
    flash_mma<<<128, 256, FLASH_SMEM_BYTES>>>(out);
}

// round 6
// speedup vs baseline: 1.1830x; 1.1830x over previous
#include <cuda_runtime.h>
#include <cstdint>

#define NTOK 8192
#define CDIM 1024
#define DDIM 64
#define BM 128
#define BN 128
#define SPLITS 2
#define KEYS_PER_SPLIT (NTOK / SPLITS)
#define CHUNKS (KEYS_PER_SPLIT / BN)

// scratch (allocation-free)
__device__ float g_q[NTOK * DDIM];
__device__ float g_k[NTOK * DDIM];
__device__ float g_v[NTOK * DDIM];
__device__ float g_po[SPLITS * NTOK * DDIM];   // partial O
__device__ float g_pl[SPLITS * NTOK];          // partial l

// m16n8k8 tf32 HMMA (base-target instruction)
__device__ __forceinline__ void mma_tf32(float* c, const uint32_t* a,
                                         uint32_t b0, uint32_t b1) {
    asm volatile(
        "mma.sync.aligned.m16n8k8.row.col.f32.tf32.tf32.f32 "
        "{%0,%1,%2,%3}, {%4,%5,%6,%7}, {%8,%9}, {%0,%1,%2,%3};"
        : "+f"(c[0]), "+f"(c[1]), "+f"(c[2]), "+f"(c[3])
        : "r"(a[0]), "r"(a[1]), "r"(a[2]), "r"(a[3]), "r"(b0), "r"(b1));
}
__device__ __forceinline__ float tf32r(float v) {
    uint32_t u;
    asm("cvt.rna.tf32.f32 %0, %1;" : "=r"(u) : "f"(v));
    return __uint_as_float(u);
}
__device__ __forceinline__ void cp_async16(float* smem_ptr, const float* gptr) {
    uint32_t sa = (uint32_t)__cvta_generic_to_shared(smem_ptr);
    asm volatile("cp.async.cg.shared.global [%0], [%1], 16;"
                 :: "r"(sa), "l"(gptr) : "memory");
}
#define CP_COMMIT() asm volatile("cp.async.commit_group;" ::: "memory")
#define CP_WAIT1()  asm volatile("cp.async.wait_group 1;" ::: "memory")

// ---------------------------------------------------------------------------
// Kernel 1: QKV projection on tf32 MMA, 2-term x-split (unchanged)
// ---------------------------------------------------------------------------
#define QP 36
__global__ __launch_bounds__(256, 1) void qkv_mma(
    const float* __restrict__ x,
    const float* __restrict__ Wq, const float* __restrict__ bq,
    const float* __restrict__ Wk, const float* __restrict__ bk,
    const float* __restrict__ Wv, const float* __restrict__ bv)
{
    __shared__ float xh[64 * QP];
    __shared__ float xl[64 * QP];
    __shared__ float ws[192 * QP];

    const int tid  = threadIdx.x;
    const int warp = tid >> 5;
    const int lane = tid & 31;
    const int g    = lane >> 2;
    const int t4   = lane & 3;
    const int xg   = g & 4;
    const int wm   = warp & 3;
    const int nh   = warp >> 2;
    const int row0 = blockIdx.x * 64;

    const int xr_r[2]  = { (0 * 256 + tid) >> 3, (1 * 256 + tid) >> 3 };
    const int xr_c4    = tid & 7;
    const float* xptr[2];
    float* xsh[2];
    float* xsl[2];
#pragma unroll
    for (int i = 0; i < 2; i++) {
        xptr[i] = x + (size_t)(row0 + xr_r[i]) * CDIM + xr_c4 * 4;
        int sc = (xr_c4 * 4) ^ (xr_r[i] & 4);
        xsh[i] = xh + xr_r[i] * QP + sc;
        xsl[i] = xl + xr_r[i] * QP + sc;
    }
    const float* wptr[6];
    float* wss[6];
#pragma unroll
    for (int i = 0; i < 6; i++) {
        int idx = i * 256 + tid;
        int j = idx >> 3, c4 = idx & 7;
        const float* Wp = (j < 64) ? Wq : ((j < 128) ? Wk : Wv);
        wptr[i] = Wp + (size_t)(j & 63) * CDIM + c4 * 4;
        wss[i]  = ws + j * QP + ((c4 * 4) ^ (j & 4));
    }

    float4 xreg[2], wreg[6];
#pragma unroll
    for (int i = 0; i < 2; i++) xreg[i] = *(const float4*)(xptr[i]);
#pragma unroll
    for (int i = 0; i < 6; i++) wreg[i] = *(const float4*)(wptr[i]);

    float oacc[12][4];
#pragma unroll
    for (int n = 0; n < 12; n++)
#pragma unroll
        for (int j = 0; j < 4; j++) oacc[n][j] = 0.f;

    for (int kc = 0; kc < 32; kc++) {
        __syncthreads();
#pragma unroll
        for (int i = 0; i < 2; i++) {
            float4 h, l;
            h.x = tf32r(xreg[i].x); l.x = tf32r(xreg[i].x - h.x);
            h.y = tf32r(xreg[i].y); l.y = tf32r(xreg[i].y - h.y);
            h.z = tf32r(xreg[i].z); l.z = tf32r(xreg[i].z - h.z);
            h.w = tf32r(xreg[i].w); l.w = tf32r(xreg[i].w - h.w);
            *(float4*)(xsh[i]) = h;
            *(float4*)(xsl[i]) = l;
        }
#pragma unroll
        for (int i = 0; i < 6; i++) {
            float4 w4 = wreg[i];
            w4.x = tf32r(w4.x); w4.y = tf32r(w4.y);
            w4.z = tf32r(w4.z); w4.w = tf32r(w4.w);
            *(float4*)(wss[i]) = w4;
        }
        __syncthreads();

        if (kc < 31) {
#pragma unroll
            for (int i = 0; i < 2; i++)
                xreg[i] = *(const float4*)(xptr[i] + (kc + 1) * 32);
#pragma unroll
            for (int i = 0; i < 6; i++)
                wreg[i] = *(const float4*)(wptr[i] + (kc + 1) * 32);
        }

        const float* xhr0 = xh + (wm * 16 + g) * QP;
        const float* xhr1 = xh + (wm * 16 + g + 8) * QP;
        const float* xlr0 = xl + (wm * 16 + g) * QP;
        const float* xlr1 = xl + (wm * 16 + g + 8) * QP;
#pragma unroll
        for (int kk = 0; kk < 4; kk++) {
            int c0 = (8 * kk + t4) ^ xg;
            int c1 = (8 * kk + t4 + 4) ^ xg;
            uint32_t ah[4], al[4];
            ah[0] = __float_as_uint(xhr0[c0]);
            ah[1] = __float_as_uint(xhr1[c0]);
            ah[2] = __float_as_uint(xhr0[c1]);
            ah[3] = __float_as_uint(xhr1[c1]);
            al[0] = __float_as_uint(xlr0[c0]);
            al[1] = __float_as_uint(xlr1[c0]);
            al[2] = __float_as_uint(xlr0[c1]);
            al[3] = __float_as_uint(xlr1[c1]);
#pragma unroll
            for (int n = 0; n < 12; n++) {
                const float* wb = ws + (nh * 96 + 8 * n + g) * QP;
                uint32_t b0 = __float_as_uint(wb[c0]);
                uint32_t b1 = __float_as_uint(wb[c1]);
                mma_tf32(oacc[n], ah, b0, b1);
                mma_tf32(oacc[n], al, b0, b1);
            }
        }
    }

    const int r0 = row0 + wm * 16 + g;
#pragma unroll
    for (int n = 0; n < 12; n++) {
        int cb = nh * 96 + 8 * n + 2 * t4;
        float* dst;
        int col;
        const float* bp;
        if (cb < 64)       { dst = g_q; col = cb;       bp = bq; }
        else if (cb < 128) { dst = g_k; col = cb - 64;  bp = bk; }
        else               { dst = g_v; col = cb - 128; bp = bv; }
        float2 bias = *(const float2*)(bp + col);
        *(float2*)(dst + (size_t)r0 * DDIM + col) =
            make_float2(oacc[n][0] + bias.x, oacc[n][1] + bias.y);
        *(float2*)(dst + (size_t)(r0 + 8) * DDIM + col) =
            make_float2(oacc[n][2] + bias.x, oacc[n][3] + bias.y);
    }
}

// ---------------------------------------------------------------------------
// Kernel 2: flash attention. BM=128, split-KV=2, 2 m16-tiles per warp
// (B-fragment reuse x2), cp.async double-buffered K/V staging.
// grid (64, 2), 256 thr = 4 m-warps x 2 col-halves.
// ---------------------------------------------------------------------------
#define KPITCH 72
#define PPITCH 136
// float offsets in dynamic smem
#define OFF_K0 0
#define OFF_K1 (128 * KPITCH)
#define OFF_V0 (2 * 128 * KPITCH)
#define OFF_V1 (3 * 128 * KPITCH)
#define OFF_P  (4 * 128 * KPITCH)
#define OFF_L  (OFF_P + 128 * PPITCH)
#define FLASH_SMEM_BYTES ((OFF_L + 256) * 4)

__global__ __launch_bounds__(256, 1) void flash_mma()
{
    extern __shared__ float sm[];

    const int tid   = threadIdx.x;
    const int warp  = tid >> 5;
    const int lane  = tid & 31;
    const int g     = lane >> 2;
    const int t4    = lane & 3;
    const int xg    = g & 4;
    const int wm    = warp & 3;      // m-warp: 32 rows
    const int nh    = warp >> 2;     // col half
    const int wr0   = wm * 32;
    const int row0  = blockIdx.x * BM;
    const int split = blockIdx.y;
    const int key0  = split * KEYS_PER_SPLIT;

    // stage Q (128 x 64) into the P region (pitch KPITCH), preload A-frags
#pragma unroll
    for (int i = 0; i < 8; i++) {
        int idx = i * 256 + tid;
        int r = idx >> 4, c4 = idx & 15;
        float4 v = *(const float4*)(g_q + (size_t)(row0 + r) * DDIM + c4 * 4);
        *(float4*)(sm + OFF_P + r * KPITCH + ((c4 * 4) ^ (r & 4))) = v;
    }
    __syncthreads();

    uint32_t aQ[2][8][4];
#pragma unroll
    for (int m = 0; m < 2; m++) {
        const float* qr0 = sm + OFF_P + (wr0 + m * 16 + g) * KPITCH;
        const float* qr1 = qr0 + 8 * KPITCH;
#pragma unroll
        for (int kk = 0; kk < 8; kk++) {
            int c0 = (8 * kk + t4) ^ xg;
            int c1 = (8 * kk + t4 + 4) ^ xg;
            aQ[m][kk][0] = __float_as_uint(qr0[c0]);
            aQ[m][kk][1] = __float_as_uint(qr1[c0]);
            aQ[m][kk][2] = __float_as_uint(qr0[c1]);
            aQ[m][kk][3] = __float_as_uint(qr1[c1]);
        }
    }
    __syncthreads();   // P region free for reuse

    // staging coordinates (16 cp.async per thread per chunk)
    int st_r[8], st_sc[8];
#pragma unroll
    for (int i = 0; i < 8; i++) {
        int idx = i * 256 + tid;
        st_r[i]  = idx >> 4;
        int c4   = idx & 15;
        st_sc[i] = st_r[i] * KPITCH + ((c4 * 4) ^ (st_r[i] & 4));
    }

    // issue chunk 0 into buffer 0
#pragma unroll
    for (int i = 0; i < 8; i++) {
        const float* gk = g_k + (size_t)(key0 + st_r[i]) * DDIM + ((i * 256 + tid) & 15) * 4;
        const float* gv = g_v + (size_t)(key0 + st_r[i]) * DDIM + ((i * 256 + tid) & 15) * 4;
        cp_async16(sm + OFF_K0 + st_sc[i], gk);
        cp_async16(sm + OFF_V0 + st_sc[i], gv);
    }
    CP_COMMIT();

    float oacc[2][4][4];
#pragma unroll
    for (int m = 0; m < 2; m++)
#pragma unroll
        for (int n = 0; n < 4; n++)
#pragma unroll
            for (int j = 0; j < 4; j++) oacc[m][n][j] = 0.f;
    float lac[2][2] = {{0.f, 0.f}, {0.f, 0.f}};

    for (int ch = 0; ch < CHUNKS; ch++) {
        __syncthreads();   // all warps done reading buffer (ch+1)&1 from iter ch-1

        // prefetch next chunk into the other buffer
        if (ch + 1 < CHUNKS) {
            const size_t nb = (size_t)(key0 + (ch + 1) * BN);
            const int kb_off = ((ch + 1) & 1) ? OFF_K1 : OFF_K0;
            const int vb_off = ((ch + 1) & 1) ? OFF_V1 : OFF_V0;
#pragma unroll
            for (int i = 0; i < 8; i++) {
                int c4 = (i * 256 + tid) & 15;
                cp_async16(sm + kb_off + st_sc[i],
                           g_k + (nb + st_r[i]) * DDIM + c4 * 4);
                cp_async16(sm + vb_off + st_sc[i],
                           g_v + (nb + st_r[i]) * DDIM + c4 * 4);
            }
        }
        CP_COMMIT();
        CP_WAIT1();        // chunk ch's group complete
        __syncthreads();

        const float* Ks = sm + ((ch & 1) ? OFF_K1 : OFF_K0);
        const float* Vs = sm + ((ch & 1) ? OFF_V1 : OFF_V0);

        // S = Q K^T : 2 m-tiles x 8 n-tiles, kk outer (16 indep chains),
        // each B fragment feeds 2 MMAs.
        float sacc[2][8][4];
#pragma unroll
        for (int m = 0; m < 2; m++)
#pragma unroll
            for (int n = 0; n < 8; n++)
#pragma unroll
                for (int j = 0; j < 4; j++) sacc[m][n][j] = 0.f;
#pragma unroll
        for (int kk = 0; kk < 8; kk++) {
            int c0 = (8 * kk + t4) ^ xg;
            int c1 = (8 * kk + t4 + 4) ^ xg;
#pragma unroll
            for (int n = 0; n < 8; n++) {
                const float* kb = Ks + (8 * (nh * 8 + n) + g) * KPITCH;
                uint32_t b0 = __float_as_uint(kb[c0]);
                uint32_t b1 = __float_as_uint(kb[c1]);
                mma_tf32(sacc[0][n], aQ[0][kk], b0, b1);
                mma_tf32(sacc[1][n], aQ[1][kk], b0, b1);
            }
        }

        // exp + P store + l accumulation
#pragma unroll
        for (int m = 0; m < 2; m++) {
            float* pr0 = sm + OFF_P + (wr0 + m * 16 + g) * PPITCH;
            float* pr1 = pr0 + 8 * PPITCH;
#pragma unroll
            for (int n = 0; n < 8; n++) {
                float p0 = __expf(sacc[m][n][0] * 0.03125f);
                float p1 = __expf(sacc[m][n][1] * 0.03125f);
                float p2 = __expf(sacc[m][n][2] * 0.03125f);
                float p3 = __expf(sacc[m][n][3] * 0.03125f);
                lac[m][0] += p0 + p1;
                lac[m][1] += p2 + p3;
                int pc = (8 * (nh * 8 + n) + 2 * t4) ^ xg;
                *(float2*)(pr0 + pc) = make_float2(p0, p1);
                *(float2*)(pr1 + pc) = make_float2(p2, p3);
            }
        }
        __syncthreads();   // both col-halves of P complete

        // O += P @ V : per k2, aP per m-tile and V fragments per n reused x2
#pragma unroll
        for (int k2 = 0; k2 < 16; k2++) {
            int c0 = (8 * k2 + t4) ^ xg;
            int c1 = (8 * k2 + t4 + 4) ^ xg;
            uint32_t aP[2][4];
#pragma unroll
            for (int m = 0; m < 2; m++) {
                const float* pr0 = sm + OFF_P + (wr0 + m * 16 + g) * PPITCH;
                const float* pr1 = pr0 + 8 * PPITCH;
                aP[m][0] = __float_as_uint(pr0[c0]);
                aP[m][1] = __float_as_uint(pr1[c0]);
                aP[m][2] = __float_as_uint(pr0[c1]);
                aP[m][3] = __float_as_uint(pr1[c1]);
            }
            const float* vb0 = Vs + (8 * k2 + t4) * KPITCH;
            const float* vb1 = Vs + (8 * k2 + t4 + 4) * KPITCH;
#pragma unroll
            for (int n = 0; n < 4; n++) {
                int col = 32 * nh + 8 * n + g;
                uint32_t b0 = __float_as_uint(vb0[col]);
                uint32_t b1 = __float_as_uint(vb1[col ^ 4]);
                mma_tf32(oacc[0][n], aP[0], b0, b1);
                mma_tf32(oacc[1][n], aP[1], b0, b1);
            }
        }
    }

    // reduce l over the t4 quad; publish per-half sums, combine halves
#pragma unroll
    for (int m = 0; m < 2; m++)
#pragma unroll
        for (int h = 0; h < 2; h++) {
            lac[m][h] += __shfl_xor_sync(0xffffffffu, lac[m][h], 1);
            lac[m][h] += __shfl_xor_sync(0xffffffffu, lac[m][h], 2);
        }
    float* lh = sm + OFF_L;
    if (t4 == 0) {
#pragma unroll
        for (int m = 0; m < 2; m++) {
            lh[nh * 128 + wr0 + m * 16 + g]     = lac[m][0];
            lh[nh * 128 + wr0 + m * 16 + g + 8] = lac[m][1];
        }
    }
    __syncthreads();
    if (tid < 128)
        g_pl[(size_t)split * NTOK + row0 + tid] = lh[tid] + lh[128 + tid];

    // write partial O
#pragma unroll
    for (int m = 0; m < 2; m++) {
        const size_t r0 = (size_t)split * NTOK + row0 + wr0 + m * 16 + g;
#pragma unroll
        for (int n = 0; n < 4; n++) {
            int col = 32 * nh + 8 * n + 2 * t4;
            *(float2*)(g_po + r0 * DDIM + col) =
                make_float2(oacc[m][n][0], oacc[m][n][1]);
            *(float2*)(g_po + (r0 + 8) * DDIM + col) =
                make_float2(oacc[m][n][2], oacc[m][n][3]);
        }
    }
}

// ---------------------------------------------------------------------------
// Kernel 3: merge split-KV partials, write 16x-tiled output
// ---------------------------------------------------------------------------
__global__ __launch_bounds__(256, 1) void merge_kernel(float* __restrict__ out)
{
    int g   = blockIdx.x * 256 + threadIdx.x;
    int row = g >> 4;
    int cg  = (g & 15) * 4;
    float l   = g_pl[row] + g_pl[NTOK + row];
    float inv = 1.f / l;
    float4 a = *(const float4*)(g_po + (size_t)row * DDIM + cg);
    float4 b = *(const float4*)(g_po + (size_t)(NTOK + row) * DDIM + cg);
    float4 y = make_float4((a.x + b.x) * inv, (a.y + b.y) * inv,
                           (a.z + b.z) * inv, (a.w + b.w) * inv);
    float* op = out + (size_t)row * 1024 + cg;
#pragma unroll
    for (int h = 0; h < 16; h++) *(float4*)(op + h * 64) = y;
}

// ---------------------------------------------------------------------------
extern "C" void kernel_launch(void* const* d_in, const int* in_sizes, int n_in,
                              void* d_out, int out_size)
{
    const float* x  = (const float*)d_in[0];
    const float* Wq = (const float*)d_in[1];
    const float* bq = (const float*)d_in[2];
    const float* Wk = (const float*)d_in[3];
    const float* bk = (const float*)d_in[4];
    const float* Wv = (const float*)d_in[5];
    const float* bv = (const float*)d_in[6];
    float* out = (float*)d_out;

    qkv_mma<<<128, 256>>>(x, Wq, bq, Wk, bk, Wv, bv);

    cudaFuncSetAttribute(flash_mma, cudaFuncAttributeMaxDynamicSharedMemorySize,
                         FLASH_SMEM_BYTES);
    flash_mma<<<dim3(64, 2), 256, FLASH_SMEM_BYTES>>>();

    merge_kernel<<<512, 256>>>(out);
}

// round 7
// speedup vs baseline: 1.9503x; 1.6486x over previous
#include <cuda_runtime.h>
#include <cuda_fp16.h>
#include <cstdint>

#define NTOK 8192
#define CDIM 1024
#define DDIM 64
#define BM 128
#define BN 128
#define SPLITS 2
#define KEYS_PER_SPLIT (NTOK / SPLITS)
#define CHUNKS (KEYS_PER_SPLIT / BN)

// scratch (allocation-free)
__device__ __half g_qh[NTOK * DDIM];
__device__ __half g_kh[NTOK * DDIM];
__device__ __half g_vT[DDIM * NTOK];           // V^T, half [d][tok]
__device__ float  g_po[SPLITS * NTOK * DDIM];  // partial O
__device__ float  g_pl[SPLITS * NTOK];         // partial l

// m16n8k16 fp16 HMMA, fp32 accumulate (base-target instruction)
__device__ __forceinline__ void mma_f16(float* c, const uint32_t* a,
                                        uint32_t b0, uint32_t b1) {
    asm volatile(
        "mma.sync.aligned.m16n8k16.row.col.f32.f16.f16.f32 "
        "{%0,%1,%2,%3}, {%4,%5,%6,%7}, {%8,%9}, {%0,%1,%2,%3};"
        : "+f"(c[0]), "+f"(c[1]), "+f"(c[2]), "+f"(c[3])
        : "r"(a[0]), "r"(a[1]), "r"(a[2]), "r"(a[3]), "r"(b0), "r"(b1));
}
__device__ __forceinline__ void cp_async16(const void* smem_ptr, const void* gptr) {
    uint32_t sa = (uint32_t)__cvta_generic_to_shared(smem_ptr);
    asm volatile("cp.async.cg.shared.global [%0], [%1], 16;"
                 :: "r"(sa), "l"(gptr) : "memory");
}
#define CP_COMMIT() asm volatile("cp.async.commit_group;" ::: "memory")
#define CP_WAIT1()  asm volatile("cp.async.wait_group 1;" ::: "memory")

__device__ __forceinline__ uint32_t h2(float a, float b) {
    __half2 h = __floats2half2_rn(a, b);
    return *(uint32_t*)&h;
}
__device__ __forceinline__ uint32_t ldsm_u32(const __half* p) {
    return *(const uint32_t*)p;
}

// ---------------------------------------------------------------------------
// Kernel 1: QKV projection, fp16 MMA with 2-term x-split.
// C[8192 x 192] = x @ [Wq|Wk|Wv]^T. grid 128 CTAs (64 rows), 256 thr =
// 4 m-warps x 2 n-halves (96 cols). K chunks of 32 (2 k16 steps).
// ---------------------------------------------------------------------------
#define XP 40
__global__ __launch_bounds__(256, 1) void qkv_mma(
    const float* __restrict__ x,
    const float* __restrict__ Wq, const float* __restrict__ bq,
    const float* __restrict__ Wk, const float* __restrict__ bk,
    const float* __restrict__ Wv, const float* __restrict__ bv)
{
    __shared__ __half xh[64 * XP];
    __shared__ __half xl[64 * XP];
    __shared__ __half ws[192 * XP];

    const int tid  = threadIdx.x;
    const int warp = tid >> 5;
    const int lane = tid & 31;
    const int g    = lane >> 2;
    const int t4   = lane & 3;
    const int wm   = warp & 3;
    const int nh   = warp >> 2;
    const int row0 = blockIdx.x * 64;

    // staging coordinates
    const int xr[2] = { tid >> 3, (256 + tid) >> 3 };
    const int xc4   = tid & 7;
    const float* xptr[2];
#pragma unroll
    for (int i = 0; i < 2; i++)
        xptr[i] = x + (size_t)(row0 + xr[i]) * CDIM + xc4 * 4;

    const float* wptr[6];
    int wj[6];
#pragma unroll
    for (int i = 0; i < 6; i++) {
        int idx = i * 256 + tid;
        wj[i] = idx >> 3;
        int c4 = idx & 7;
        const float* Wp = (wj[i] < 64) ? Wq : ((wj[i] < 128) ? Wk : Wv);
        wptr[i] = Wp + (size_t)(wj[i] & 63) * CDIM + c4 * 4;
    }

    float4 xreg[2], wreg[6];
#pragma unroll
    for (int i = 0; i < 2; i++) xreg[i] = *(const float4*)(xptr[i]);
#pragma unroll
    for (int i = 0; i < 6; i++) wreg[i] = *(const float4*)(wptr[i]);

    float oacc[12][4];
#pragma unroll
    for (int n = 0; n < 12; n++)
#pragma unroll
        for (int j = 0; j < 4; j++) oacc[n][j] = 0.f;

    for (int kc = 0; kc < 32; kc++) {
        __syncthreads();
        // split x into fp16 hi/lo, round W to fp16, store to smem
#pragma unroll
        for (int i = 0; i < 2; i++) {
            float4 v = xreg[i];
            __half hx = __float2half_rn(v.x), hy = __float2half_rn(v.y);
            __half hz = __float2half_rn(v.z), hw = __float2half_rn(v.w);
            uint2 hi, lo;
            hi.x = h2(__half2float(hx), __half2float(hy));
            hi.y = h2(__half2float(hz), __half2float(hw));
            // repack exact hi halves (avoid double rounding): overwrite with originals
            __half2 h01; h01.x = hx; h01.y = hy; hi.x = *(uint32_t*)&h01;
            __half2 h23; h23.x = hz; h23.y = hw; hi.y = *(uint32_t*)&h23;
            lo.x = h2(v.x - __half2float(hx), v.y - __half2float(hy));
            lo.y = h2(v.z - __half2float(hz), v.w - __half2float(hw));
            int base = xr[i] * XP + xc4 * 4;
            *(uint2*)(xh + base) = hi;
            *(uint2*)(xl + base) = lo;
        }
#pragma unroll
        for (int i = 0; i < 6; i++) {
            float4 v = wreg[i];
            uint2 w2;
            w2.x = h2(v.x, v.y);
            w2.y = h2(v.z, v.w);
            int idx = i * 256 + tid;
            *(uint2*)(ws + wj[i] * XP + (idx & 7) * 4) = w2;
        }
        __syncthreads();

        if (kc < 31) {
#pragma unroll
            for (int i = 0; i < 2; i++)
                xreg[i] = *(const float4*)(xptr[i] + (kc + 1) * 32);
#pragma unroll
            for (int i = 0; i < 6; i++)
                wreg[i] = *(const float4*)(wptr[i] + (kc + 1) * 32);
        }

        const __half* xhr0 = xh + (wm * 16 + g) * XP;
        const __half* xhr1 = xhr0 + 8 * XP;
        const __half* xlr0 = xl + (wm * 16 + g) * XP;
        const __half* xlr1 = xlr0 + 8 * XP;
#pragma unroll
        for (int kk = 0; kk < 2; kk++) {
            int c0 = 16 * kk + 2 * t4;
            uint32_t ah[4], al[4];
            ah[0] = ldsm_u32(xhr0 + c0);
            ah[1] = ldsm_u32(xhr1 + c0);
            ah[2] = ldsm_u32(xhr0 + c0 + 8);
            ah[3] = ldsm_u32(xhr1 + c0 + 8);
            al[0] = ldsm_u32(xlr0 + c0);
            al[1] = ldsm_u32(xlr1 + c0);
            al[2] = ldsm_u32(xlr0 + c0 + 8);
            al[3] = ldsm_u32(xlr1 + c0 + 8);
#pragma unroll
            for (int n = 0; n < 12; n++) {
                const __half* wb = ws + (nh * 96 + 8 * n + g) * XP + c0;
                uint32_t b0 = ldsm_u32(wb);
                uint32_t b1 = ldsm_u32(wb + 8);
                mma_f16(oacc[n], ah, b0, b1);
                mma_f16(oacc[n], al, b0, b1);
            }
        }
    }

    // epilogue: bias add, write half outputs (q/k row-major, v transposed)
    const int r0 = row0 + wm * 16 + g;
#pragma unroll
    for (int n = 0; n < 12; n++) {
        int cb = nh * 96 + 8 * n + 2 * t4;
        if (cb < 64) {
            float2 bias = *(const float2*)(bq + cb);
            *(uint32_t*)(g_qh + (size_t)r0 * DDIM + cb) =
                h2(oacc[n][0] + bias.x, oacc[n][1] + bias.y);
            *(uint32_t*)(g_qh + (size_t)(r0 + 8) * DDIM + cb) =
                h2(oacc[n][2] + bias.x, oacc[n][3] + bias.y);
        } else if (cb < 128) {
            int col = cb - 64;
            float2 bias = *(const float2*)(bk + col);
            *(uint32_t*)(g_kh + (size_t)r0 * DDIM + col) =
                h2(oacc[n][0] + bias.x, oacc[n][1] + bias.y);
            *(uint32_t*)(g_kh + (size_t)(r0 + 8) * DDIM + col) =
                h2(oacc[n][2] + bias.x, oacc[n][3] + bias.y);
        } else {
            int col = cb - 128;
            float bx = bv[col], by = bv[col + 1];
            g_vT[(size_t)col * NTOK + r0]           = __float2half_rn(oacc[n][0] + bx);
            g_vT[(size_t)(col + 1) * NTOK + r0]     = __float2half_rn(oacc[n][1] + by);
            g_vT[(size_t)col * NTOK + r0 + 8]       = __float2half_rn(oacc[n][2] + bx);
            g_vT[(size_t)(col + 1) * NTOK + r0 + 8] = __float2half_rn(oacc[n][3] + by);
        }
    }
}

// ---------------------------------------------------------------------------
// Kernel 2: fp16 flash attention. BM=128, split-KV=2, cp.async double-buffered,
// 2 m16-tiles per warp. grid (64, 2), 256 thr = 4 m-warps x 2 col-halves.
// smem (halfs): K0|K1 (128x72 each) | V0|V1 (64x136 each, V^T) | P (128x136)
// ---------------------------------------------------------------------------
#define KP 72
#define VP 136
#define PP 136
#define HK0 0
#define HK1 (128 * KP)
#define HV0 (2 * 128 * KP)
#define HV1 (HV0 + 64 * VP)
#define HP  (HV1 + 64 * VP)
#define HEND (HP + 128 * PP)
#define FLASH_SMEM_BYTES (HEND * 2 + 256 * 4 + 16)

__global__ __launch_bounds__(256, 1) void flash_mma()
{
    extern __shared__ __half smh[];
    float* lh = (float*)(smh + HEND);

    const int tid   = threadIdx.x;
    const int warp  = tid >> 5;
    const int lane  = tid & 31;
    const int g     = lane >> 2;
    const int t4    = lane & 3;
    const int wm    = warp & 3;
    const int nh    = warp >> 2;
    const int wr0   = wm * 32;
    const int row0  = blockIdx.x * BM;
    const int split = blockIdx.y;
    const int key0  = split * KEYS_PER_SPLIT;

    // load Q A-fragments directly from global (one-time)
    uint32_t aQ[2][4][4];
#pragma unroll
    for (int m = 0; m < 2; m++) {
        const __half* q0 = g_qh + (size_t)(row0 + wr0 + m * 16 + g) * DDIM;
        const __half* q1 = q0 + 8 * DDIM;
#pragma unroll
        for (int kk = 0; kk < 4; kk++) {
            int c0 = 16 * kk + 2 * t4;
            aQ[m][kk][0] = *(const uint32_t*)(q0 + c0);
            aQ[m][kk][1] = *(const uint32_t*)(q1 + c0);
            aQ[m][kk][2] = *(const uint32_t*)(q0 + c0 + 8);
            aQ[m][kk][3] = *(const uint32_t*)(q1 + c0 + 8);
        }
    }

    // cp.async staging coordinates: K 4 ops/thread, V^T 4 ops/thread
    int kr[4], kc8[4], vr[4], vc8[4];
#pragma unroll
    for (int i = 0; i < 4; i++) {
        int idx = i * 256 + tid;
        kr[i] = idx >> 3;  kc8[i] = (idx & 7) * 8;
        vr[i] = idx >> 4;  vc8[i] = (idx & 15) * 8;
    }

    // issue chunk 0 into buffer 0
#pragma unroll
    for (int i = 0; i < 4; i++) {
        cp_async16(smh + HK0 + kr[i] * KP + kc8[i],
                   g_kh + (size_t)(key0 + kr[i]) * DDIM + kc8[i]);
        cp_async16(smh + HV0 + vr[i] * VP + vc8[i],
                   g_vT + (size_t)vr[i] * NTOK + key0 + vc8[i]);
    }
    CP_COMMIT();

    float oacc[2][4][4];
#pragma unroll
    for (int m = 0; m < 2; m++)
#pragma unroll
        for (int n = 0; n < 4; n++)
#pragma unroll
            for (int j = 0; j < 4; j++) oacc[m][n][j] = 0.f;
    float lac[2][2] = {{0.f, 0.f}, {0.f, 0.f}};

    for (int ch = 0; ch < CHUNKS; ch++) {
        __syncthreads();   // prior reads of the buffer being refilled are done

        if (ch + 1 < CHUNKS) {
            const size_t nb = (size_t)(key0 + (ch + 1) * BN);
            __half* kb = smh + (((ch + 1) & 1) ? HK1 : HK0);
            __half* vb = smh + (((ch + 1) & 1) ? HV1 : HV0);
#pragma unroll
            for (int i = 0; i < 4; i++) {
                cp_async16(kb + kr[i] * KP + kc8[i],
                           g_kh + (nb + kr[i]) * DDIM + kc8[i]);
                cp_async16(vb + vr[i] * VP + vc8[i],
                           g_vT + (size_t)vr[i] * NTOK + nb + vc8[i]);
            }
        }
        CP_COMMIT();
        CP_WAIT1();
        __syncthreads();

        const __half* Ks = smh + ((ch & 1) ? HK1 : HK0);
        const __half* Vs = smh + ((ch & 1) ? HV1 : HV0);

        // S = Q K^T : 2 m-tiles x 8 n-tiles, kk outer
        float sacc[2][8][4];
#pragma unroll
        for (int m = 0; m < 2; m++)
#pragma unroll
            for (int n = 0; n < 8; n++)
#pragma unroll
                for (int j = 0; j < 4; j++) sacc[m][n][j] = 0.f;
#pragma unroll
        for (int kk = 0; kk < 4; kk++) {
            int c0 = 16 * kk + 2 * t4;
#pragma unroll
            for (int n = 0; n < 8; n++) {
                const __half* kb = Ks + (8 * (nh * 8 + n) + g) * KP + c0;
                uint32_t b0 = ldsm_u32(kb);
                uint32_t b1 = ldsm_u32(kb + 8);
                mma_f16(sacc[0][n], aQ[0][kk], b0, b1);
                mma_f16(sacc[1][n], aQ[1][kk], b0, b1);
            }
        }

        // exp, accumulate l, store P (half2)
#pragma unroll
        for (int m = 0; m < 2; m++) {
            __half* pr0 = smh + HP + (wr0 + m * 16 + g) * PP;
            __half* pr1 = pr0 + 8 * PP;
#pragma unroll
            for (int n = 0; n < 8; n++) {
                float p0 = __expf(sacc[m][n][0] * 0.03125f);
                float p1 = __expf(sacc[m][n][1] * 0.03125f);
                float p2 = __expf(sacc[m][n][2] * 0.03125f);
                float p3 = __expf(sacc[m][n][3] * 0.03125f);
                lac[m][0] += p0 + p1;
                lac[m][1] += p2 + p3;
                int pc = nh * 64 + 8 * n + 2 * t4;
                *(uint32_t*)(pr0 + pc) = h2(p0, p1);
                *(uint32_t*)(pr1 + pc) = h2(p2, p3);
            }
        }
        __syncthreads();   // both col-halves of P complete

        // O += P @ V : 8 k16-steps over 128 keys
#pragma unroll
        for (int k2 = 0; k2 < 8; k2++) {
            int c0 = 16 * k2 + 2 * t4;
            uint32_t aP[2][4];
#pragma unroll
            for (int m = 0; m < 2; m++) {
                const __half* pr0 = smh + HP + (wr0 + m * 16 + g) * PP + c0;
                const __half* pr1 = pr0 + 8 * PP;
                aP[m][0] = ldsm_u32(pr0);
                aP[m][1] = ldsm_u32(pr1);
                aP[m][2] = ldsm_u32(pr0 + 8);
                aP[m][3] = ldsm_u32(pr1 + 8);
            }
#pragma unroll
            for (int n = 0; n < 4; n++) {
                const __half* vb = Vs + (nh * 32 + 8 * n + g) * VP + c0;
                uint32_t b0 = ldsm_u32(vb);
                uint32_t b1 = ldsm_u32(vb + 8);
                mma_f16(oacc[0][n], aP[0], b0, b1);
                mma_f16(oacc[1][n], aP[1], b0, b1);
            }
        }
    }

    // reduce l over the t4 quad; publish per-half sums, combine halves
#pragma unroll
    for (int m = 0; m < 2; m++)
#pragma unroll
        for (int h = 0; h < 2; h++) {
            lac[m][h] += __shfl_xor_sync(0xffffffffu, lac[m][h], 1);
            lac[m][h] += __shfl_xor_sync(0xffffffffu, lac[m][h], 2);
        }
    if (t4 == 0) {
#pragma unroll
        for (int m = 0; m < 2; m++) {
            lh[nh * 128 + wr0 + m * 16 + g]     = lac[m][0];
            lh[nh * 128 + wr0 + m * 16 + g + 8] = lac[m][1];
        }
    }
    __syncthreads();
    if (tid < 128)
        g_pl[(size_t)split * NTOK + row0 + tid] = lh[tid] + lh[128 + tid];

    // write partial O
#pragma unroll
    for (int m = 0; m < 2; m++) {
        const size_t r0 = (size_t)split * NTOK + row0 + wr0 + m * 16 + g;
#pragma unroll
        for (int n = 0; n < 4; n++) {
            int col = 32 * nh + 8 * n + 2 * t4;
            *(float2*)(g_po + r0 * DDIM + col) =
                make_float2(oacc[m][n][0], oacc[m][n][1]);
            *(float2*)(g_po + (r0 + 8) * DDIM + col) =
                make_float2(oacc[m][n][2], oacc[m][n][3]);
        }
    }
}

// ---------------------------------------------------------------------------
// Kernel 3: merge split-KV partials, write 16x-tiled output
// ---------------------------------------------------------------------------
__global__ __launch_bounds__(256, 1) void merge_kernel(float* __restrict__ out)
{
    int g   = blockIdx.x * 256 + threadIdx.x;
    int row = g >> 4;
    int cg  = (g & 15) * 4;
    float l   = g_pl[row] + g_pl[NTOK + row];
    float inv = 1.f / l;
    float4 a = *(const float4*)(g_po + (size_t)row * DDIM + cg);
    float4 b = *(const float4*)(g_po + (size_t)(NTOK + row) * DDIM + cg);
    float4 y = make_float4((a.x + b.x) * inv, (a.y + b.y) * inv,
                           (a.z + b.z) * inv, (a.w + b.w) * inv);
    float* op = out + (size_t)row * 1024 + cg;
#pragma unroll
    for (int h = 0; h < 16; h++) *(float4*)(op + h * 64) = y;
}

// ---------------------------------------------------------------------------
extern "C" void kernel_launch(void* const* d_in, const int* in_sizes, int n_in,
                              void* d_out, int out_size)
{
    const float* x  = (const float*)d_in[0];
    const float* Wq = (const float*)d_in[1];
    const float* bq = (const float*)d_in[2];
    const float* Wk = (const float*)d_in[3];
    const float* bk = (const float*)d_in[4];
    const float* Wv = (const float*)d_in[5];
    const float* bv = (const float*)d_in[6];
    float* out = (float*)d_out;

    qkv_mma<<<128, 256>>>(x, Wq, bq, Wk, bk, Wv, bv);

    cudaFuncSetAttribute(flash_mma, cudaFuncAttributeMaxDynamicSharedMemorySize,
                         FLASH_SMEM_BYTES);
    flash_mma<<<dim3(64, 2), 256, FLASH_SMEM_BYTES>>>();

    merge_kernel<<<512, 256>>>(out);
}

// round 8
// speedup vs baseline: 2.1174x; 1.0857x over previous
#include <cuda_runtime.h>
#include <cuda_fp16.h>
#include <cstdint>

#define NTOK 8192
#define CDIM 1024
#define DDIM 64
#define BM 128
#define BN 128
#define SPLITS 2
#define KEYS_PER_SPLIT (NTOK / SPLITS)
#define CHUNKS (KEYS_PER_SPLIT / BN)

// scratch (allocation-free)
__device__ __half g_qh[NTOK * DDIM];
__device__ __half g_kh[NTOK * DDIM];
__device__ __half g_vT[DDIM * NTOK];           // V^T, half [d][tok]
__device__ float  g_po[SPLITS * NTOK * DDIM];  // partial O
__device__ float  g_pl[SPLITS * NTOK];         // partial l

// m16n8k16 fp16 HMMA, fp32 accumulate
__device__ __forceinline__ void mma_f16(float* c, const uint32_t* a,
                                        uint32_t b0, uint32_t b1) {
    asm volatile(
        "mma.sync.aligned.m16n8k16.row.col.f32.f16.f16.f32 "
        "{%0,%1,%2,%3}, {%4,%5,%6,%7}, {%8,%9}, {%0,%1,%2,%3};"
        : "+f"(c[0]), "+f"(c[1]), "+f"(c[2]), "+f"(c[3])
        : "r"(a[0]), "r"(a[1]), "r"(a[2]), "r"(a[3]), "r"(b0), "r"(b1));
}
__device__ __forceinline__ void ldsm_x4(uint32_t& r0, uint32_t& r1,
                                        uint32_t& r2, uint32_t& r3,
                                        const __half* p) {
    uint32_t a = (uint32_t)__cvta_generic_to_shared(p);
    asm volatile("ldmatrix.sync.aligned.m8n8.x4.shared.b16 {%0,%1,%2,%3}, [%4];"
                 : "=r"(r0), "=r"(r1), "=r"(r2), "=r"(r3) : "r"(a));
}
__device__ __forceinline__ void cp_async16(const void* smem_ptr, const void* gptr) {
    uint32_t sa = (uint32_t)__cvta_generic_to_shared(smem_ptr);
    asm volatile("cp.async.cg.shared.global [%0], [%1], 16;"
                 :: "r"(sa), "l"(gptr) : "memory");
}
#define CP_COMMIT() asm volatile("cp.async.commit_group;" ::: "memory")
#define CP_WAIT1()  asm volatile("cp.async.wait_group 1;" ::: "memory")

__device__ __forceinline__ uint32_t h2(float a, float b) {
    __half2 h = __floats2half2_rn(a, b);
    return *(uint32_t*)&h;
}

// ---------------------------------------------------------------------------
// Kernel 1: QKV projection, fp16 MMA + x hi/lo split. K-chunks of 64.
// grid 128 CTAs (64 rows), 256 thr = 4 m-warps x 2 n-halves (96 cols).
// ---------------------------------------------------------------------------
#define XP 72
__global__ __launch_bounds__(256, 1) void qkv_mma(
    const float* __restrict__ x,
    const float* __restrict__ Wq, const float* __restrict__ bq,
    const float* __restrict__ Wk, const float* __restrict__ bk,
    const float* __restrict__ Wv, const float* __restrict__ bv)
{
    __shared__ __half xh[64 * XP];
    __shared__ __half xl[64 * XP];
    __shared__ __half ws[192 * XP];

    const int tid  = threadIdx.x;
    const int warp = tid >> 5;
    const int lane = tid & 31;
    const int r8   = lane & 7;
    const int hA   = (lane >> 3) & 1;
    const int hB   = lane >> 4;
    const int wm   = warp & 3;
    const int nh   = warp >> 2;
    const int row0 = blockIdx.x * 64;

    // staging coordinates: x 4 float4/thread, W 12 float4/thread (chunk=64)
    int xr[4], xc[4];
    const float* xptr[4];
#pragma unroll
    for (int i = 0; i < 4; i++) {
        int idx = i * 256 + tid;
        xr[i] = idx >> 4; xc[i] = (idx & 15) * 4;
        xptr[i] = x + (size_t)(row0 + xr[i]) * CDIM + xc[i];
    }
    int wj[12], wc[12];
    const float* wptr[12];
#pragma unroll
    for (int i = 0; i < 12; i++) {
        int idx = i * 256 + tid;
        wj[i] = idx >> 4; wc[i] = (idx & 15) * 4;
        const float* Wp = (wj[i] < 64) ? Wq : ((wj[i] < 128) ? Wk : Wv);
        wptr[i] = Wp + (size_t)(wj[i] & 63) * CDIM + wc[i];
    }

    float4 xreg[4], wreg[12];
#pragma unroll
    for (int i = 0; i < 4; i++)  xreg[i] = *(const float4*)(xptr[i]);
#pragma unroll
    for (int i = 0; i < 12; i++) wreg[i] = *(const float4*)(wptr[i]);

    float oacc[12][4];
#pragma unroll
    for (int n = 0; n < 12; n++)
#pragma unroll
        for (int j = 0; j < 4; j++) oacc[n][j] = 0.f;

    for (int kc = 0; kc < 16; kc++) {
        __syncthreads();
        // convert + store staged registers
#pragma unroll
        for (int i = 0; i < 4; i++) {
            float4 v = xreg[i];
            __half2 h01 = __floats2half2_rn(v.x, v.y);
            __half2 h23 = __floats2half2_rn(v.z, v.w);
            uint2 hi, lo;
            hi.x = *(uint32_t*)&h01; hi.y = *(uint32_t*)&h23;
            lo.x = h2(v.x - __low2float(h01), v.y - __high2float(h01));
            lo.y = h2(v.z - __low2float(h23), v.w - __high2float(h23));
            int base = xr[i] * XP + xc[i];
            *(uint2*)(xh + base) = hi;
            *(uint2*)(xl + base) = lo;
        }
#pragma unroll
        for (int i = 0; i < 12; i++) {
            float4 v = wreg[i];
            uint2 w2;
            w2.x = h2(v.x, v.y);
            w2.y = h2(v.z, v.w);
            *(uint2*)(ws + wj[i] * XP + wc[i]) = w2;
        }
        __syncthreads();

        if (kc < 15) {
#pragma unroll
            for (int i = 0; i < 4; i++)
                xreg[i] = *(const float4*)(xptr[i] + (kc + 1) * 64);
#pragma unroll
            for (int i = 0; i < 12; i++)
                wreg[i] = *(const float4*)(wptr[i] + (kc + 1) * 64);
        }

        // MMA: 4 k16-steps, ldmatrix fragments
#pragma unroll
        for (int kk = 0; kk < 4; kk++) {
            uint32_t ah[4], al[4];
            const __half* xa = xh + (wm * 16 + 8 * hA + r8) * XP + 16 * kk + 8 * hB;
            const __half* xb = xl + (wm * 16 + 8 * hA + r8) * XP + 16 * kk + 8 * hB;
            ldsm_x4(ah[0], ah[1], ah[2], ah[3], xa);
            ldsm_x4(al[0], al[1], al[2], al[3], xb);
#pragma unroll
            for (int np = 0; np < 6; np++) {
                uint32_t b00, b01, b10, b11;
                const __half* wb = ws + (nh * 96 + 16 * np + 8 * hB + r8) * XP
                                      + 16 * kk + 8 * hA;
                ldsm_x4(b00, b01, b10, b11, wb);
                mma_f16(oacc[2 * np],     ah, b00, b01);
                mma_f16(oacc[2 * np],     al, b00, b01);
                mma_f16(oacc[2 * np + 1], ah, b10, b11);
                mma_f16(oacc[2 * np + 1], al, b10, b11);
            }
        }
    }

    // epilogue: bias add, half outputs (q/k row-major, v transposed)
    const int g  = lane >> 2;
    const int t4 = lane & 3;
    const int r0 = row0 + wm * 16 + g;
#pragma unroll
    for (int n = 0; n < 12; n++) {
        int cb = nh * 96 + 8 * n + 2 * t4;
        if (cb < 64) {
            float2 bias = *(const float2*)(bq + cb);
            *(uint32_t*)(g_qh + (size_t)r0 * DDIM + cb) =
                h2(oacc[n][0] + bias.x, oacc[n][1] + bias.y);
            *(uint32_t*)(g_qh + (size_t)(r0 + 8) * DDIM + cb) =
                h2(oacc[n][2] + bias.x, oacc[n][3] + bias.y);
        } else if (cb < 128) {
            int col = cb - 64;
            float2 bias = *(const float2*)(bk + col);
            *(uint32_t*)(g_kh + (size_t)r0 * DDIM + col) =
                h2(oacc[n][0] + bias.x, oacc[n][1] + bias.y);
            *(uint32_t*)(g_kh + (size_t)(r0 + 8) * DDIM + col) =
                h2(oacc[n][2] + bias.x, oacc[n][3] + bias.y);
        } else {
            int col = cb - 128;
            float bx = bv[col], by = bv[col + 1];
            g_vT[(size_t)col * NTOK + r0]           = __float2half_rn(oacc[n][0] + bx);
            g_vT[(size_t)(col + 1) * NTOK + r0]     = __float2half_rn(oacc[n][1] + by);
            g_vT[(size_t)col * NTOK + r0 + 8]       = __float2half_rn(oacc[n][2] + bx);
            g_vT[(size_t)(col + 1) * NTOK + r0 + 8] = __float2half_rn(oacc[n][3] + by);
        }
    }
}

// ---------------------------------------------------------------------------
// Kernel 2: fp16 flash attention with ldmatrix fragments.
// BM=128, split-KV=2, cp.async double-buffered. grid (64,2), 256 thr.
// ---------------------------------------------------------------------------
#define KP 72
#define VP 136
#define PP 136
#define HK0 0
#define HK1 (128 * KP)
#define HV0 (2 * 128 * KP)
#define HV1 (HV0 + 64 * VP)
#define HP  (HV1 + 64 * VP)
#define HEND (HP + 128 * PP)
#define FLASH_SMEM_BYTES (HEND * 2 + 256 * 4 + 16)

__global__ __launch_bounds__(256, 1) void flash_mma()
{
    extern __shared__ __half smh[];
    float* lh = (float*)(smh + HEND);

    const int tid   = threadIdx.x;
    const int warp  = tid >> 5;
    const int lane  = tid & 31;
    const int r8    = lane & 7;
    const int hA    = (lane >> 3) & 1;
    const int hB    = lane >> 4;
    const int g     = lane >> 2;
    const int t4    = lane & 3;
    const int wm    = warp & 3;
    const int nh    = warp >> 2;
    const int wr0   = wm * 32;
    const int row0  = blockIdx.x * BM;
    const int split = blockIdx.y;
    const int key0  = split * KEYS_PER_SPLIT;

    // Q A-fragments from global (one-time)
    uint32_t aQ[2][4][4];
#pragma unroll
    for (int m = 0; m < 2; m++) {
        const __half* q0 = g_qh + (size_t)(row0 + wr0 + m * 16 + g) * DDIM;
        const __half* q1 = q0 + 8 * DDIM;
#pragma unroll
        for (int kk = 0; kk < 4; kk++) {
            int c0 = 16 * kk + 2 * t4;
            aQ[m][kk][0] = *(const uint32_t*)(q0 + c0);
            aQ[m][kk][1] = *(const uint32_t*)(q1 + c0);
            aQ[m][kk][2] = *(const uint32_t*)(q0 + c0 + 8);
            aQ[m][kk][3] = *(const uint32_t*)(q1 + c0 + 8);
        }
    }

    // cp.async staging coordinates
    int kr[4], kc8[4], vr[4], vc8[4];
#pragma unroll
    for (int i = 0; i < 4; i++) {
        int idx = i * 256 + tid;
        kr[i] = idx >> 3;  kc8[i] = (idx & 7) * 8;
        vr[i] = idx >> 4;  vc8[i] = (idx & 15) * 8;
    }
#pragma unroll
    for (int i = 0; i < 4; i++) {
        cp_async16(smh + HK0 + kr[i] * KP + kc8[i],
                   g_kh + (size_t)(key0 + kr[i]) * DDIM + kc8[i]);
        cp_async16(smh + HV0 + vr[i] * VP + vc8[i],
                   g_vT + (size_t)vr[i] * NTOK + key0 + vc8[i]);
    }
    CP_COMMIT();

    float oacc[2][4][4];
#pragma unroll
    for (int m = 0; m < 2; m++)
#pragma unroll
        for (int n = 0; n < 4; n++)
#pragma unroll
            for (int j = 0; j < 4; j++) oacc[m][n][j] = 0.f;
    float lac[2][2] = {{0.f, 0.f}, {0.f, 0.f}};

    for (int ch = 0; ch < CHUNKS; ch++) {
        __syncthreads();

        if (ch + 1 < CHUNKS) {
            const size_t nb = (size_t)(key0 + (ch + 1) * BN);
            __half* kb = smh + (((ch + 1) & 1) ? HK1 : HK0);
            __half* vb = smh + (((ch + 1) & 1) ? HV1 : HV0);
#pragma unroll
            for (int i = 0; i < 4; i++) {
                cp_async16(kb + kr[i] * KP + kc8[i],
                           g_kh + (nb + kr[i]) * DDIM + kc8[i]);
                cp_async16(vb + vr[i] * VP + vc8[i],
                           g_vT + (size_t)vr[i] * NTOK + nb + vc8[i]);
            }
        }
        CP_COMMIT();
        CP_WAIT1();
        __syncthreads();

        const __half* Ks = smh + ((ch & 1) ? HK1 : HK0);
        const __half* Vs = smh + ((ch & 1) ? HV1 : HV0);

        // S = Q K^T : kk outer, np pairs via ldmatrix.x4
        float sacc[2][8][4];
#pragma unroll
        for (int m = 0; m < 2; m++)
#pragma unroll
            for (int n = 0; n < 8; n++)
#pragma unroll
                for (int j = 0; j < 4; j++) sacc[m][n][j] = 0.f;
#pragma unroll
        for (int kk = 0; kk < 4; kk++) {
#pragma unroll
            for (int np = 0; np < 4; np++) {
                uint32_t b00, b01, b10, b11;
                const __half* kb = Ks + (nh * 64 + 16 * np + 8 * hB + r8) * KP
                                      + 16 * kk + 8 * hA;
                ldsm_x4(b00, b01, b10, b11, kb);
                mma_f16(sacc[0][2 * np],     aQ[0][kk], b00, b01);
                mma_f16(sacc[1][2 * np],     aQ[1][kk], b00, b01);
                mma_f16(sacc[0][2 * np + 1], aQ[0][kk], b10, b11);
                mma_f16(sacc[1][2 * np + 1], aQ[1][kk], b10, b11);
            }
        }

        // exp, accumulate l, store P (half2)
#pragma unroll
        for (int m = 0; m < 2; m++) {
            __half* pr0 = smh + HP + (wr0 + m * 16 + g) * PP;
            __half* pr1 = pr0 + 8 * PP;
#pragma unroll
            for (int n = 0; n < 8; n++) {
                float p0 = __expf(sacc[m][n][0] * 0.03125f);
                float p1 = __expf(sacc[m][n][1] * 0.03125f);
                float p2 = __expf(sacc[m][n][2] * 0.03125f);
                float p3 = __expf(sacc[m][n][3] * 0.03125f);
                lac[m][0] += p0 + p1;
                lac[m][1] += p2 + p3;
                int pc = nh * 64 + 8 * n + 2 * t4;
                *(uint32_t*)(pr0 + pc) = h2(p0, p1);
                *(uint32_t*)(pr1 + pc) = h2(p2, p3);
            }
        }
        __syncthreads();

        // O += P @ V : ldmatrix for both aP and V fragments
#pragma unroll
        for (int k2 = 0; k2 < 8; k2++) {
            uint32_t aP[2][4];
#pragma unroll
            for (int m = 0; m < 2; m++) {
                const __half* pa = smh + HP + (wr0 + m * 16 + 8 * hA + r8) * PP
                                       + 16 * k2 + 8 * hB;
                ldsm_x4(aP[m][0], aP[m][1], aP[m][2], aP[m][3], pa);
            }
#pragma unroll
            for (int np = 0; np < 2; np++) {
                uint32_t v00, v01, v10, v11;
                const __half* vb = Vs + (nh * 32 + 16 * np + 8 * hB + r8) * VP
                                      + 16 * k2 + 8 * hA;
                ldsm_x4(v00, v01, v10, v11, vb);
                mma_f16(oacc[0][2 * np],     aP[0], v00, v01);
                mma_f16(oacc[1][2 * np],     aP[1], v00, v01);
                mma_f16(oacc[0][2 * np + 1], aP[0], v10, v11);
                mma_f16(oacc[1][2 * np + 1], aP[1], v10, v11);
            }
        }
    }

    // reduce l over the t4 quad; combine col-halves via smem
#pragma unroll
    for (int m = 0; m < 2; m++)
#pragma unroll
        for (int h = 0; h < 2; h++) {
            lac[m][h] += __shfl_xor_sync(0xffffffffu, lac[m][h], 1);
            lac[m][h] += __shfl_xor_sync(0xffffffffu, lac[m][h], 2);
        }
    if (t4 == 0) {
#pragma unroll
        for (int m = 0; m < 2; m++) {
            lh[nh * 128 + wr0 + m * 16 + g]     = lac[m][0];
            lh[nh * 128 + wr0 + m * 16 + g + 8] = lac[m][1];
        }
    }
    __syncthreads();
    if (tid < 128)
        g_pl[(size_t)split * NTOK + row0 + tid] = lh[tid] + lh[128 + tid];

    // write partial O
#pragma unroll
    for (int m = 0; m < 2; m++) {
        const size_t r0 = (size_t)split * NTOK + row0 + wr0 + m * 16 + g;
#pragma unroll
        for (int n = 0; n < 4; n++) {
            int col = 32 * nh + 8 * n + 2 * t4;
            *(float2*)(g_po + r0 * DDIM + col) =
                make_float2(oacc[m][n][0], oacc[m][n][1]);
            *(float2*)(g_po + (r0 + 8) * DDIM + col) =
                make_float2(oacc[m][n][2], oacc[m][n][3]);
        }
    }
}

// ---------------------------------------------------------------------------
// Kernel 3: merge split-KV partials, write 16x-tiled output
// ---------------------------------------------------------------------------
__global__ __launch_bounds__(256, 1) void merge_kernel(float* __restrict__ out)
{
    int g   = blockIdx.x * 256 + threadIdx.x;
    int row = g >> 4;
    int cg  = (g & 15) * 4;
    float l   = g_pl[row] + g_pl[NTOK + row];
    float inv = 1.f / l;
    float4 a = *(const float4*)(g_po + (size_t)row * DDIM + cg);
    float4 b = *(const float4*)(g_po + (size_t)(NTOK + row) * DDIM + cg);
    float4 y = make_float4((a.x + b.x) * inv, (a.y + b.y) * inv,
                           (a.z + b.z) * inv, (a.w + b.w) * inv);
    float* op = out + (size_t)row * 1024 + cg;
#pragma unroll
    for (int h = 0; h < 16; h++) *(float4*)(op + h * 64) = y;
}

// ---------------------------------------------------------------------------
extern "C" void kernel_launch(void* const* d_in, const int* in_sizes, int n_in,
                              void* d_out, int out_size)
{
    const float* x  = (const float*)d_in[0];
    const float* Wq = (const float*)d_in[1];
    const float* bq = (const float*)d_in[2];
    const float* Wk = (const float*)d_in[3];
    const float* bk = (const float*)d_in[4];
    const float* Wv = (const float*)d_in[5];
    const float* bv = (const float*)d_in[6];
    float* out = (float*)d_out;

    qkv_mma<<<128, 256>>>(x, Wq, bq, Wk, bk, Wv, bv);

    cudaFuncSetAttribute(flash_mma, cudaFuncAttributeMaxDynamicSharedMemorySize,
                         FLASH_SMEM_BYTES);
    flash_mma<<<dim3(64, 2), 256, FLASH_SMEM_BYTES>>>();

    merge_kernel<<<512, 256>>>(out);
}

// round 9
// speedup vs baseline: 2.3893x; 1.1284x over previous
#include <cuda_runtime.h>
#include <cuda_fp16.h>
#include <cstdint>

#define NTOK 8192
#define CDIM 1024
#define DDIM 64
#define BM 128
#define BN 128
#define SPLITS 2
#define KEYS_PER_SPLIT (NTOK / SPLITS)
#define CHUNKS (KEYS_PER_SPLIT / BN)

// q pre-scale: log2(e)/32 so S accumulators are base-2 exponents
#define QSCALE 0.045084220027780106f

// scratch (allocation-free)
__device__ __half g_qh[NTOK * DDIM];
__device__ __half g_kh[NTOK * DDIM];
__device__ __half g_vT[DDIM * NTOK];           // V^T, half [d][tok]
__device__ float  g_po[SPLITS * NTOK * DDIM];  // partial O
__device__ float  g_pl[SPLITS * NTOK];         // partial l

// m16n8k16 fp16 HMMA, fp32 accumulate
__device__ __forceinline__ void mma_f16(float* c, const uint32_t* a,
                                        uint32_t b0, uint32_t b1) {
    asm volatile(
        "mma.sync.aligned.m16n8k16.row.col.f32.f16.f16.f32 "
        "{%0,%1,%2,%3}, {%4,%5,%6,%7}, {%8,%9}, {%0,%1,%2,%3};"
        : "+f"(c[0]), "+f"(c[1]), "+f"(c[2]), "+f"(c[3])
        : "r"(a[0]), "r"(a[1]), "r"(a[2]), "r"(a[3]), "r"(b0), "r"(b1));
}
__device__ __forceinline__ void ldsm_x4(uint32_t& r0, uint32_t& r1,
                                        uint32_t& r2, uint32_t& r3,
                                        const __half* p) {
    uint32_t a = (uint32_t)__cvta_generic_to_shared(p);
    asm volatile("ldmatrix.sync.aligned.m8n8.x4.shared.b16 {%0,%1,%2,%3}, [%4];"
                 : "=r"(r0), "=r"(r1), "=r"(r2), "=r"(r3) : "r"(a));
}
__device__ __forceinline__ void cp_async16(const void* smem_ptr, const void* gptr) {
    uint32_t sa = (uint32_t)__cvta_generic_to_shared(smem_ptr);
    asm volatile("cp.async.cg.shared.global [%0], [%1], 16;"
                 :: "r"(sa), "l"(gptr) : "memory");
}
#define CP_COMMIT() asm volatile("cp.async.commit_group;" ::: "memory")
#define CP_WAIT1()  asm volatile("cp.async.wait_group 1;" ::: "memory")

__device__ __forceinline__ uint32_t h2(float a, float b) {
    __half2 h = __floats2half2_rn(a, b);
    return *(uint32_t*)&h;
}
__device__ __forceinline__ uint32_t ex2_f16x2(uint32_t a) {
    uint32_t d;
    asm("ex2.approx.f16x2 %0, %1;" : "=r"(d) : "r"(a));
    return d;
}

// ---------------------------------------------------------------------------
// Kernel 1: QKV projection, fp16 MMA. x hi/lo split compensation applied to
// the V output tiles only (v errors land 1:1 in y; q/k errors are /32-damped).
// q written pre-scaled by QSCALE. grid 128 CTAs (64 rows), 256 thr.
// ---------------------------------------------------------------------------
#define XP 72
__global__ __launch_bounds__(256, 1) void qkv_mma(
    const float* __restrict__ x,
    const float* __restrict__ Wq, const float* __restrict__ bq,
    const float* __restrict__ Wk, const float* __restrict__ bk,
    const float* __restrict__ Wv, const float* __restrict__ bv)
{
    __shared__ __half xh[64 * XP];
    __shared__ __half xl[64 * XP];
    __shared__ __half ws[192 * XP];

    const int tid  = threadIdx.x;
    const int warp = tid >> 5;
    const int lane = tid & 31;
    const int r8   = lane & 7;
    const int hA   = (lane >> 3) & 1;
    const int hB   = lane >> 4;
    const int wm   = warp & 3;
    const int nh   = warp >> 2;
    const int row0 = blockIdx.x * 64;

    int xr[4], xc[4];
    const float* xptr[4];
#pragma unroll
    for (int i = 0; i < 4; i++) {
        int idx = i * 256 + tid;
        xr[i] = idx >> 4; xc[i] = (idx & 15) * 4;
        xptr[i] = x + (size_t)(row0 + xr[i]) * CDIM + xc[i];
    }
    int wj[12], wc[12];
    const float* wptr[12];
#pragma unroll
    for (int i = 0; i < 12; i++) {
        int idx = i * 256 + tid;
        wj[i] = idx >> 4; wc[i] = (idx & 15) * 4;
        const float* Wp = (wj[i] < 64) ? Wq : ((wj[i] < 128) ? Wk : Wv);
        wptr[i] = Wp + (size_t)(wj[i] & 63) * CDIM + wc[i];
    }

    float4 xreg[4], wreg[12];
#pragma unroll
    for (int i = 0; i < 4; i++)  xreg[i] = *(const float4*)(xptr[i]);
#pragma unroll
    for (int i = 0; i < 12; i++) wreg[i] = *(const float4*)(wptr[i]);

    float oacc[12][4];
#pragma unroll
    for (int n = 0; n < 12; n++)
#pragma unroll
        for (int j = 0; j < 4; j++) oacc[n][j] = 0.f;

    for (int kc = 0; kc < 16; kc++) {
        __syncthreads();
#pragma unroll
        for (int i = 0; i < 4; i++) {
            float4 v = xreg[i];
            __half2 h01 = __floats2half2_rn(v.x, v.y);
            __half2 h23 = __floats2half2_rn(v.z, v.w);
            uint2 hi, lo;
            hi.x = *(uint32_t*)&h01; hi.y = *(uint32_t*)&h23;
            lo.x = h2(v.x - __low2float(h01), v.y - __high2float(h01));
            lo.y = h2(v.z - __low2float(h23), v.w - __high2float(h23));
            int base = xr[i] * XP + xc[i];
            *(uint2*)(xh + base) = hi;
            *(uint2*)(xl + base) = lo;
        }
#pragma unroll
        for (int i = 0; i < 12; i++) {
            float4 v = wreg[i];
            uint2 w2;
            w2.x = h2(v.x, v.y);
            w2.y = h2(v.z, v.w);
            *(uint2*)(ws + wj[i] * XP + wc[i]) = w2;
        }
        __syncthreads();

        if (kc < 15) {
#pragma unroll
            for (int i = 0; i < 4; i++)
                xreg[i] = *(const float4*)(xptr[i] + (kc + 1) * 64);
#pragma unroll
            for (int i = 0; i < 12; i++)
                wreg[i] = *(const float4*)(wptr[i] + (kc + 1) * 64);
        }

#pragma unroll
        for (int kk = 0; kk < 4; kk++) {
            uint32_t ah[4], al[4];
            const __half* xa = xh + (wm * 16 + 8 * hA + r8) * XP + 16 * kk + 8 * hB;
            const __half* xb = xl + (wm * 16 + 8 * hA + r8) * XP + 16 * kk + 8 * hB;
            ldsm_x4(ah[0], ah[1], ah[2], ah[3], xa);
            ldsm_x4(al[0], al[1], al[2], al[3], xb);
#pragma unroll
            for (int np = 0; np < 6; np++) {
                uint32_t b00, b01, b10, b11;
                const __half* wb = ws + (nh * 96 + 16 * np + 8 * hB + r8) * XP
                                      + 16 * kk + 8 * hA;
                ldsm_x4(b00, b01, b10, b11, wb);
                mma_f16(oacc[2 * np],     ah, b00, b01);
                mma_f16(oacc[2 * np + 1], ah, b10, b11);
                if (nh == 1 && np >= 2) {   // V tiles: add lo compensation
                    mma_f16(oacc[2 * np],     al, b00, b01);
                    mma_f16(oacc[2 * np + 1], al, b10, b11);
                }
            }
        }
    }

    const int g  = lane >> 2;
    const int t4 = lane & 3;
    const int r0 = row0 + wm * 16 + g;
#pragma unroll
    for (int n = 0; n < 12; n++) {
        int cb = nh * 96 + 8 * n + 2 * t4;
        if (cb < 64) {
            float2 bias = *(const float2*)(bq + cb);
            *(uint32_t*)(g_qh + (size_t)r0 * DDIM + cb) =
                h2((oacc[n][0] + bias.x) * QSCALE, (oacc[n][1] + bias.y) * QSCALE);
            *(uint32_t*)(g_qh + (size_t)(r0 + 8) * DDIM + cb) =
                h2((oacc[n][2] + bias.x) * QSCALE, (oacc[n][3] + bias.y) * QSCALE);
        } else if (cb < 128) {
            int col = cb - 64;
            float2 bias = *(const float2*)(bk + col);
            *(uint32_t*)(g_kh + (size_t)r0 * DDIM + col) =
                h2(oacc[n][0] + bias.x, oacc[n][1] + bias.y);
            *(uint32_t*)(g_kh + (size_t)(r0 + 8) * DDIM + col) =
                h2(oacc[n][2] + bias.x, oacc[n][3] + bias.y);
        } else {
            int col = cb - 128;
            float bx = bv[col], by = bv[col + 1];
            g_vT[(size_t)col * NTOK + r0]           = __float2half_rn(oacc[n][0] + bx);
            g_vT[(size_t)(col + 1) * NTOK + r0]     = __float2half_rn(oacc[n][1] + by);
            g_vT[(size_t)col * NTOK + r0 + 8]       = __float2half_rn(oacc[n][2] + bx);
            g_vT[(size_t)(col + 1) * NTOK + r0 + 8] = __float2half_rn(oacc[n][3] + by);
        }
    }
}

// ---------------------------------------------------------------------------
// Kernel 2: fp16 flash attention, ldmatrix fragments, ex2.f16x2 softmax.
// BM=128, split-KV=2, cp.async double-buffered. grid (64,2), 256 thr.
// ---------------------------------------------------------------------------
#define KP 72
#define VP 136
#define PP 136
#define HK0 0
#define HK1 (128 * KP)
#define HV0 (2 * 128 * KP)
#define HV1 (HV0 + 64 * VP)
#define HP  (HV1 + 64 * VP)
#define HEND (HP + 128 * PP)
#define FLASH_SMEM_BYTES (HEND * 2 + 256 * 4 + 16)

__global__ __launch_bounds__(256, 1) void flash_mma()
{
    extern __shared__ __half smh[];
    float* lh = (float*)(smh + HEND);

    const int tid   = threadIdx.x;
    const int warp  = tid >> 5;
    const int lane  = tid & 31;
    const int r8    = lane & 7;
    const int hA    = (lane >> 3) & 1;
    const int hB    = lane >> 4;
    const int g     = lane >> 2;
    const int t4    = lane & 3;
    const int wm    = warp & 3;
    const int nh    = warp >> 2;
    const int wr0   = wm * 32;
    const int row0  = blockIdx.x * BM;
    const int split = blockIdx.y;
    const int key0  = split * KEYS_PER_SPLIT;

    // Q A-fragments from global (q already pre-scaled by QSCALE)
    uint32_t aQ[2][4][4];
#pragma unroll
    for (int m = 0; m < 2; m++) {
        const __half* q0 = g_qh + (size_t)(row0 + wr0 + m * 16 + g) * DDIM;
        const __half* q1 = q0 + 8 * DDIM;
#pragma unroll
        for (int kk = 0; kk < 4; kk++) {
            int c0 = 16 * kk + 2 * t4;
            aQ[m][kk][0] = *(const uint32_t*)(q0 + c0);
            aQ[m][kk][1] = *(const uint32_t*)(q1 + c0);
            aQ[m][kk][2] = *(const uint32_t*)(q0 + c0 + 8);
            aQ[m][kk][3] = *(const uint32_t*)(q1 + c0 + 8);
        }
    }

    int kr[4], kc8[4], vr[4], vc8[4];
#pragma unroll
    for (int i = 0; i < 4; i++) {
        int idx = i * 256 + tid;
        kr[i] = idx >> 3;  kc8[i] = (idx & 7) * 8;
        vr[i] = idx >> 4;  vc8[i] = (idx & 15) * 8;
    }
#pragma unroll
    for (int i = 0; i < 4; i++) {
        cp_async16(smh + HK0 + kr[i] * KP + kc8[i],
                   g_kh + (size_t)(key0 + kr[i]) * DDIM + kc8[i]);
        cp_async16(smh + HV0 + vr[i] * VP + vc8[i],
                   g_vT + (size_t)vr[i] * NTOK + key0 + vc8[i]);
    }
    CP_COMMIT();

    float oacc[2][4][4];
#pragma unroll
    for (int m = 0; m < 2; m++)
#pragma unroll
        for (int n = 0; n < 4; n++)
#pragma unroll
            for (int j = 0; j < 4; j++) oacc[m][n][j] = 0.f;
    float lac[2][2] = {{0.f, 0.f}, {0.f, 0.f}};

    for (int ch = 0; ch < CHUNKS; ch++) {
        __syncthreads();

        if (ch + 1 < CHUNKS) {
            const size_t nb = (size_t)(key0 + (ch + 1) * BN);
            __half* kb = smh + (((ch + 1) & 1) ? HK1 : HK0);
            __half* vb = smh + (((ch + 1) & 1) ? HV1 : HV0);
#pragma unroll
            for (int i = 0; i < 4; i++) {
                cp_async16(kb + kr[i] * KP + kc8[i],
                           g_kh + (nb + kr[i]) * DDIM + kc8[i]);
                cp_async16(vb + vr[i] * VP + vc8[i],
                           g_vT + (size_t)vr[i] * NTOK + nb + vc8[i]);
            }
        }
        CP_COMMIT();
        CP_WAIT1();
        __syncthreads();

        const __half* Ks = smh + ((ch & 1) ? HK1 : HK0);
        const __half* Vs = smh + ((ch & 1) ? HV1 : HV0);

        // S (log2-domain scores)
        float sacc[2][8][4];
#pragma unroll
        for (int m = 0; m < 2; m++)
#pragma unroll
            for (int n = 0; n < 8; n++)
#pragma unroll
                for (int j = 0; j < 4; j++) sacc[m][n][j] = 0.f;
#pragma unroll
        for (int kk = 0; kk < 4; kk++) {
#pragma unroll
            for (int np = 0; np < 4; np++) {
                uint32_t b00, b01, b10, b11;
                const __half* kb = Ks + (nh * 64 + 16 * np + 8 * hB + r8) * KP
                                      + 16 * kk + 8 * hA;
                ldsm_x4(b00, b01, b10, b11, kb);
                mma_f16(sacc[0][2 * np],     aQ[0][kk], b00, b01);
                mma_f16(sacc[1][2 * np],     aQ[1][kk], b00, b01);
                mma_f16(sacc[0][2 * np + 1], aQ[0][kk], b10, b11);
                mma_f16(sacc[1][2 * np + 1], aQ[1][kk], b10, b11);
            }
        }

        // P = 2^S via ex2.approx.f16x2; accumulate l with HADD2
#pragma unroll
        for (int m = 0; m < 2; m++) {
            __half* pr0 = smh + HP + (wr0 + m * 16 + g) * PP;
            __half* pr1 = pr0 + 8 * PP;
            __half2 ls01 = __floats2half2_rn(0.f, 0.f);
            __half2 ls23 = ls01;
#pragma unroll
            for (int n = 0; n < 8; n++) {
                uint32_t u01 = ex2_f16x2(h2(sacc[m][n][0], sacc[m][n][1]));
                uint32_t u23 = ex2_f16x2(h2(sacc[m][n][2], sacc[m][n][3]));
                ls01 = __hadd2(ls01, *(__half2*)&u01);
                ls23 = __hadd2(ls23, *(__half2*)&u23);
                int pc = nh * 64 + 8 * n + 2 * t4;
                *(uint32_t*)(pr0 + pc) = u01;
                *(uint32_t*)(pr1 + pc) = u23;
            }
            lac[m][0] += __low2float(ls01) + __high2float(ls01);
            lac[m][1] += __low2float(ls23) + __high2float(ls23);
        }
        __syncthreads();

        // O += P @ V
#pragma unroll
        for (int k2 = 0; k2 < 8; k2++) {
            uint32_t aP[2][4];
#pragma unroll
            for (int m = 0; m < 2; m++) {
                const __half* pa = smh + HP + (wr0 + m * 16 + 8 * hA + r8) * PP
                                       + 16 * k2 + 8 * hB;
                ldsm_x4(aP[m][0], aP[m][1], aP[m][2], aP[m][3], pa);
            }
#pragma unroll
            for (int np = 0; np < 2; np++) {
                uint32_t v00, v01, v10, v11;
                const __half* vb = Vs + (nh * 32 + 16 * np + 8 * hB + r8) * VP
                                      + 16 * k2 + 8 * hA;
                ldsm_x4(v00, v01, v10, v11, vb);
                mma_f16(oacc[0][2 * np],     aP[0], v00, v01);
                mma_f16(oacc[1][2 * np],     aP[1], v00, v01);
                mma_f16(oacc[0][2 * np + 1], aP[0], v10, v11);
                mma_f16(oacc[1][2 * np + 1], aP[1], v10, v11);
            }
        }
    }

    // reduce l over the t4 quad; combine col-halves via smem
#pragma unroll
    for (int m = 0; m < 2; m++)
#pragma unroll
        for (int h = 0; h < 2; h++) {
            lac[m][h] += __shfl_xor_sync(0xffffffffu, lac[m][h], 1);
            lac[m][h] += __shfl_xor_sync(0xffffffffu, lac[m][h], 2);
        }
    if (t4 == 0) {
#pragma unroll
        for (int m = 0; m < 2; m++) {
            lh[nh * 128 + wr0 + m * 16 + g]     = lac[m][0];
            lh[nh * 128 + wr0 + m * 16 + g + 8] = lac[m][1];
        }
    }
    __syncthreads();
    if (tid < 128)
        g_pl[(size_t)split * NTOK + row0 + tid] = lh[tid] + lh[128 + tid];

#pragma unroll
    for (int m = 0; m < 2; m++) {
        const size_t r0 = (size_t)split * NTOK + row0 + wr0 + m * 16 + g;
#pragma unroll
        for (int n = 0; n < 4; n++) {
            int col = 32 * nh + 8 * n + 2 * t4;
            *(float2*)(g_po + r0 * DDIM + col) =
                make_float2(oacc[m][n][0], oacc[m][n][1]);
            *(float2*)(g_po + (r0 + 8) * DDIM + col) =
                make_float2(oacc[m][n][2], oacc[m][n][3]);
        }
    }
}

// ---------------------------------------------------------------------------
// Kernel 3: merge split-KV partials, write 16x-tiled output
// ---------------------------------------------------------------------------
__global__ __launch_bounds__(256, 1) void merge_kernel(float* __restrict__ out)
{
    int g   = blockIdx.x * 256 + threadIdx.x;
    int row = g >> 4;
    int cg  = (g & 15) * 4;
    float l   = g_pl[row] + g_pl[NTOK + row];
    float inv = 1.f / l;
    float4 a = *(const float4*)(g_po + (size_t)row * DDIM + cg);
    float4 b = *(const float4*)(g_po + (size_t)(NTOK + row) * DDIM + cg);
    float4 y = make_float4((a.x + b.x) * inv, (a.y + b.y) * inv,
                           (a.z + b.z) * inv, (a.w + b.w) * inv);
    float* op = out + (size_t)row * 1024 + cg;
#pragma unroll
    for (int h = 0; h < 16; h++) *(float4*)(op + h * 64) = y;
}

// ---------------------------------------------------------------------------
extern "C" void kernel_launch(void* const* d_in, const int* in_sizes, int n_in,
                              void* d_out, int out_size)
{
    const float* x  = (const float*)d_in[0];
    const float* Wq = (const float*)d_in[1];
    const float* bq = (const float*)d_in[2];
    const float* Wk = (const float*)d_in[3];
    const float* bk = (const float*)d_in[4];
    const float* Wv = (const float*)d_in[5];
    const float* bv = (const float*)d_in[6];
    float* out = (float*)d_out;

    qkv_mma<<<128, 256>>>(x, Wq, bq, Wk, bk, Wv, bv);

    cudaFuncSetAttribute(flash_mma, cudaFuncAttributeMaxDynamicSharedMemorySize,
                         FLASH_SMEM_BYTES);
    flash_mma<<<dim3(64, 2), 256, FLASH_SMEM_BYTES>>>();

    merge_kernel<<<512, 256>>>(out);
}

// round 10
// speedup vs baseline: 2.5781x; 1.0790x over previous
#include <cuda_runtime.h>
#include <cuda_fp16.h>
#include <cstdint>

#define NTOK 8192
#define CDIM 1024
#define DDIM 64
#define BM 128
#define BN 128
#define SPLITS 2
#define KEYS_PER_SPLIT (NTOK / SPLITS)
#define CHUNKS (KEYS_PER_SPLIT / BN)

// q pre-scale: log2(e)/32 so S accumulators are base-2 exponents
#define QSCALE 0.045084220027780106f

// scratch (allocation-free)
__device__ __half g_qh[NTOK * DDIM];
__device__ __half g_kh[NTOK * DDIM];
__device__ __half g_vT[DDIM * NTOK];           // V^T, half [d][tok]
__device__ __half g_wh[192 * CDIM];            // [Wq|Wk|Wv] in half
__device__ float  g_po[SPLITS * NTOK * DDIM];  // partial O
__device__ float  g_pl[SPLITS * NTOK];         // partial l

// m16n8k16 fp16 HMMA, fp32 accumulate
__device__ __forceinline__ void mma_f16(float* c, const uint32_t* a,
                                        uint32_t b0, uint32_t b1) {
    asm volatile(
        "mma.sync.aligned.m16n8k16.row.col.f32.f16.f16.f32 "
        "{%0,%1,%2,%3}, {%4,%5,%6,%7}, {%8,%9}, {%0,%1,%2,%3};"
        : "+f"(c[0]), "+f"(c[1]), "+f"(c[2]), "+f"(c[3])
        : "r"(a[0]), "r"(a[1]), "r"(a[2]), "r"(a[3]), "r"(b0), "r"(b1));
}
__device__ __forceinline__ void ldsm_x4(uint32_t& r0, uint32_t& r1,
                                        uint32_t& r2, uint32_t& r3,
                                        const __half* p) {
    uint32_t a = (uint32_t)__cvta_generic_to_shared(p);
    asm volatile("ldmatrix.sync.aligned.m8n8.x4.shared.b16 {%0,%1,%2,%3}, [%4];"
                 : "=r"(r0), "=r"(r1), "=r"(r2), "=r"(r3) : "r"(a));
}
__device__ __forceinline__ void cp_async16(const void* smem_ptr, const void* gptr) {
    uint32_t sa = (uint32_t)__cvta_generic_to_shared(smem_ptr);
    asm volatile("cp.async.cg.shared.global [%0], [%1], 16;"
                 :: "r"(sa), "l"(gptr) : "memory");
}
#define CP_COMMIT() asm volatile("cp.async.commit_group;" ::: "memory")
#define CP_WAIT1()  asm volatile("cp.async.wait_group 1;" ::: "memory")
#define CP_WAIT2()  asm volatile("cp.async.wait_group 2;" ::: "memory")

__device__ __forceinline__ uint32_t h2(float a, float b) {
    __half2 h = __floats2half2_rn(a, b);
    return *(uint32_t*)&h;
}
__device__ __forceinline__ uint32_t ex2_f16x2(uint32_t a) {
    uint32_t d;
    asm("ex2.approx.f16x2 %0, %1;" : "=r"(d) : "r"(a));
    return d;
}

// ---------------------------------------------------------------------------
// Kernel 0: one-time W -> half conversion ([Wq|Wk|Wv] rows, row-major 192x1024)
// ---------------------------------------------------------------------------
__global__ __launch_bounds__(256, 1) void wconv(
    const float* __restrict__ Wq, const float* __restrict__ Wk,
    const float* __restrict__ Wv)
{
    int idx  = blockIdx.x * 256 + threadIdx.x;   // 0..24575
    int base = idx * 8;
    int row  = base >> 10;
    int col  = base & 1023;
    const float* W = (row < 64) ? Wq + (size_t)row * CDIM
                   : (row < 128) ? Wk + (size_t)(row - 64) * CDIM
                                 : Wv + (size_t)(row - 128) * CDIM;
    float4 a = *(const float4*)(W + col);
    float4 b = *(const float4*)(W + col + 4);
    uint4 o;
    o.x = h2(a.x, a.y); o.y = h2(a.z, a.w);
    o.z = h2(b.x, b.y); o.w = h2(b.z, b.w);
    *(uint4*)(g_wh + base) = o;
}

// ---------------------------------------------------------------------------
// Kernel 1: QKV projection, fp16 MMA. W staged via cp.async from g_wh,
// x converted hi-only. q pre-scaled by QSCALE. grid 128, 256 thr.
// dyn smem (halfs): xh[2][64*72] | ws[2][192*72]
// ---------------------------------------------------------------------------
#define XP 72
#define XHB 4608
#define WSB 13824
#define QKV_SMEM_BYTES ((2 * XHB + 2 * WSB) * 2)

__global__ __launch_bounds__(256, 1) void qkv_mma(
    const float* __restrict__ x,
    const float* __restrict__ bq, const float* __restrict__ bk,
    const float* __restrict__ bv)
{
    extern __shared__ __half smq[];
    __half* xh = smq;                 // 2 buffers
    __half* ws = smq + 2 * XHB;       // 2 buffers

    const int tid  = threadIdx.x;
    const int warp = tid >> 5;
    const int lane = tid & 31;
    const int r8   = lane & 7;
    const int hA   = (lane >> 3) & 1;
    const int hB   = lane >> 4;
    const int wm   = warp & 3;
    const int nh   = warp >> 2;
    const int row0 = blockIdx.x * 64;

    // x staging coordinates (4 float4/thread per 64-k chunk)
    int xr[4], xc[4];
    const float* xptr[4];
#pragma unroll
    for (int i = 0; i < 4; i++) {
        int idx = i * 256 + tid;
        xr[i] = idx >> 4; xc[i] = (idx & 15) * 4;
        xptr[i] = x + (size_t)(row0 + xr[i]) * CDIM + xc[i];
    }
    // W staging coordinates (6 cp.async16/thread per chunk)
    int wr[6], wc8[6];
#pragma unroll
    for (int i = 0; i < 6; i++) {
        int idx = i * 256 + tid;
        wr[i] = idx >> 3; wc8[i] = (idx & 7) * 8;
    }

    // prologue: prefetch x chunk 0, issue W chunk 0
    float4 xreg[4];
#pragma unroll
    for (int i = 0; i < 4; i++) xreg[i] = *(const float4*)(xptr[i]);
#pragma unroll
    for (int i = 0; i < 6; i++)
        cp_async16(ws + wr[i] * XP + wc8[i], g_wh + (size_t)wr[i] * CDIM + wc8[i]);
    CP_COMMIT();

    float oacc[12][4];
#pragma unroll
    for (int n = 0; n < 12; n++)
#pragma unroll
        for (int j = 0; j < 4; j++) oacc[n][j] = 0.f;

    for (int kc = 0; kc < 16; kc++) {
        const int b = kc & 1;
        // store converted x into xh[b]
#pragma unroll
        for (int i = 0; i < 4; i++) {
            float4 v = xreg[i];
            uint2 hi;
            hi.x = h2(v.x, v.y);
            hi.y = h2(v.z, v.w);
            *(uint2*)(xh + b * XHB + xr[i] * XP + xc[i]) = hi;
        }
        __syncthreads();   // xh[b] visible; prev chunk MMA done (ws[b^1] free)

        if (kc < 15) {
#pragma unroll
            for (int i = 0; i < 6; i++)
                cp_async16(ws + (b ^ 1) * WSB + wr[i] * XP + wc8[i],
                           g_wh + (size_t)wr[i] * CDIM + (kc + 1) * 64 + wc8[i]);
        }
        CP_COMMIT();
        CP_WAIT1();        // W chunk kc ready
        __syncthreads();

        // prefetch next x chunk (overlaps MMA)
        if (kc < 15) {
#pragma unroll
            for (int i = 0; i < 4; i++)
                xreg[i] = *(const float4*)(xptr[i] + (kc + 1) * 64);
        }

        const __half* xb = xh + b * XHB;
        const __half* wb = ws + b * WSB;
#pragma unroll
        for (int kk = 0; kk < 4; kk++) {
            uint32_t ah[4];
            ldsm_x4(ah[0], ah[1], ah[2], ah[3],
                    xb + (wm * 16 + 8 * hA + r8) * XP + 16 * kk + 8 * hB);
#pragma unroll
            for (int np = 0; np < 6; np++) {
                uint32_t b00, b01, b10, b11;
                ldsm_x4(b00, b01, b10, b11,
                        wb + (nh * 96 + 16 * np + 8 * hB + r8) * XP
                           + 16 * kk + 8 * hA);
                mma_f16(oacc[2 * np],     ah, b00, b01);
                mma_f16(oacc[2 * np + 1], ah, b10, b11);
            }
        }
    }

    // epilogue: bias, half outputs
    const int g  = lane >> 2;
    const int t4 = lane & 3;
    const int r0 = row0 + wm * 16 + g;
#pragma unroll
    for (int n = 0; n < 12; n++) {
        int cb = nh * 96 + 8 * n + 2 * t4;
        if (cb < 64) {
            float2 bias = *(const float2*)(bq + cb);
            *(uint32_t*)(g_qh + (size_t)r0 * DDIM + cb) =
                h2((oacc[n][0] + bias.x) * QSCALE, (oacc[n][1] + bias.y) * QSCALE);
            *(uint32_t*)(g_qh + (size_t)(r0 + 8) * DDIM + cb) =
                h2((oacc[n][2] + bias.x) * QSCALE, (oacc[n][3] + bias.y) * QSCALE);
        } else if (cb < 128) {
            int col = cb - 64;
            float2 bias = *(const float2*)(bk + col);
            *(uint32_t*)(g_kh + (size_t)r0 * DDIM + col) =
                h2(oacc[n][0] + bias.x, oacc[n][1] + bias.y);
            *(uint32_t*)(g_kh + (size_t)(r0 + 8) * DDIM + col) =
                h2(oacc[n][2] + bias.x, oacc[n][3] + bias.y);
        } else {
            int col = cb - 128;
            float bx = bv[col], by = bv[col + 1];
            g_vT[(size_t)col * NTOK + r0]           = __float2half_rn(oacc[n][0] + bx);
            g_vT[(size_t)(col + 1) * NTOK + r0]     = __float2half_rn(oacc[n][1] + by);
            g_vT[(size_t)col * NTOK + r0 + 8]       = __float2half_rn(oacc[n][2] + bx);
            g_vT[(size_t)(col + 1) * NTOK + r0 + 8] = __float2half_rn(oacc[n][3] + by);
        }
    }
}

// ---------------------------------------------------------------------------
// Kernel 2: fp16 flash attention, register-resident P, l-via-ones-MMA,
// quad-buffered cp.async (ONE barrier per chunk). grid (64,2), 256 thr
// = 8 m-warps x 16 rows, each covering all 128 keys of a chunk.
// smem (halfs): K[4][128*72] | V[4][80*136]  (V rows 64..79: ones row + zeros)
// ---------------------------------------------------------------------------
#define KP 72
#define VP 136
#define KBUF (128 * KP)
#define VBUF (80 * VP)
#define HVBASE (4 * KBUF)
#define HEND (HVBASE + 4 * VBUF)
#define FLASH_SMEM_BYTES (HEND * 2)

__global__ __launch_bounds__(256, 1) void flash_mma()
{
    extern __shared__ __half smh[];

    const int tid   = threadIdx.x;
    const int warp  = tid >> 5;
    const int lane  = tid & 31;
    const int r8    = lane & 7;
    const int hA    = (lane >> 3) & 1;
    const int hB    = lane >> 4;
    const int g     = lane >> 2;
    const int t4    = lane & 3;
    const int wr0   = warp * 16;
    const int row0  = blockIdx.x * BM;
    const int split = blockIdx.y;
    const int key0  = split * KEYS_PER_SPLIT;

    // init ones/zero rows (64..79) of all 4 V buffers
    for (int i = tid; i < 4 * 16 * VP; i += 256) {
        int b  = i / (16 * VP);
        int rr = (i % (16 * VP)) / VP;
        int cc = i % VP;
        smh[HVBASE + b * VBUF + (64 + rr) * VP + cc] =
            (rr == 0) ? __float2half(1.f) : __float2half(0.f);
    }

    // Q A-fragments from global (pre-scaled by QSCALE)
    uint32_t aQ[4][4];
    {
        const __half* q0 = g_qh + (size_t)(row0 + wr0 + g) * DDIM;
        const __half* q1 = q0 + 8 * DDIM;
#pragma unroll
        for (int kk = 0; kk < 4; kk++) {
            int c0 = 16 * kk + 2 * t4;
            aQ[kk][0] = *(const uint32_t*)(q0 + c0);
            aQ[kk][1] = *(const uint32_t*)(q1 + c0);
            aQ[kk][2] = *(const uint32_t*)(q0 + c0 + 8);
            aQ[kk][3] = *(const uint32_t*)(q1 + c0 + 8);
        }
    }

    // staging coordinates (4 K + 4 V cp.async16 per thread per chunk)
    int kr[4], kc8[4], vr[4], vc8[4];
#pragma unroll
    for (int i = 0; i < 4; i++) {
        int idx = i * 256 + tid;
        kr[i] = idx >> 3;  kc8[i] = (idx & 7) * 8;
        vr[i] = idx >> 4;  vc8[i] = (idx & 15) * 8;
    }

    // prologue: issue chunks 0 and 1
#pragma unroll
    for (int p = 0; p < 2; p++) {
        const size_t nb = (size_t)(key0 + p * BN);
        __half* kb = smh + p * KBUF;
        __half* vb = smh + HVBASE + p * VBUF;
#pragma unroll
        for (int i = 0; i < 4; i++) {
            cp_async16(kb + kr[i] * KP + kc8[i],
                       g_kh + (nb + kr[i]) * DDIM + kc8[i]);
            cp_async16(vb + vr[i] * VP + vc8[i],
                       g_vT + (size_t)vr[i] * NTOK + nb + vc8[i]);
        }
        CP_COMMIT();
    }

    float oacc[9][4];
#pragma unroll
    for (int n = 0; n < 9; n++)
#pragma unroll
        for (int j = 0; j < 4; j++) oacc[n][j] = 0.f;

    for (int ch = 0; ch < CHUNKS; ch++) {
        // issue chunk ch+2 into buffer (ch+2)&3 (safe: laggards are in ch-1)
        if (ch + 2 < CHUNKS) {
            const size_t nb = (size_t)(key0 + (ch + 2) * BN);
            __half* kb = smh + ((ch + 2) & 3) * KBUF;
            __half* vb = smh + HVBASE + ((ch + 2) & 3) * VBUF;
#pragma unroll
            for (int i = 0; i < 4; i++) {
                cp_async16(kb + kr[i] * KP + kc8[i],
                           g_kh + (nb + kr[i]) * DDIM + kc8[i]);
                cp_async16(vb + vr[i] * VP + vc8[i],
                           g_vT + (size_t)vr[i] * NTOK + nb + vc8[i]);
            }
        }
        CP_COMMIT();
        CP_WAIT2();        // chunk ch's group complete
        __syncthreads();   // the one barrier: visibility + buffer retirement

        const __half* Ks = smh + (ch & 3) * KBUF;
        const __half* Vs = smh + HVBASE + (ch & 3) * VBUF;

        // fused S -> exp -> PV per 16-key group
#pragma unroll
        for (int j2 = 0; j2 < 8; j2++) {
            float s0[4] = {0.f, 0.f, 0.f, 0.f};
            float s1[4] = {0.f, 0.f, 0.f, 0.f};
#pragma unroll
            for (int kk = 0; kk < 4; kk++) {
                uint32_t b00, b01, b10, b11;
                ldsm_x4(b00, b01, b10, b11,
                        Ks + (16 * j2 + 8 * hB + r8) * KP + 16 * kk + 8 * hA);
                mma_f16(s0, aQ[kk], b00, b01);
                mma_f16(s1, aQ[kk], b10, b11);
            }
            // P = 2^S directly into A-fragment registers (no smem round-trip)
            uint32_t aP[4];
            aP[0] = ex2_f16x2(h2(s0[0], s0[1]));
            aP[1] = ex2_f16x2(h2(s0[2], s0[3]));
            aP[2] = ex2_f16x2(h2(s1[0], s1[1]));
            aP[3] = ex2_f16x2(h2(s1[2], s1[3]));
            // O += P @ V (8 d-tiles) and l += P @ ones (tile 8)
#pragma unroll
            for (int np = 0; np < 4; np++) {
                uint32_t v00, v01, v10, v11;
                ldsm_x4(v00, v01, v10, v11,
                        Vs + (16 * np + 8 * hB + r8) * VP + 16 * j2 + 8 * hA);
                mma_f16(oacc[2 * np],     aP, v00, v01);
                mma_f16(oacc[2 * np + 1], aP, v10, v11);
            }
            {
                uint32_t w00, w01, w10, w11;
                ldsm_x4(w00, w01, w10, w11,
                        Vs + (64 + 8 * hB + r8) * VP + 16 * j2 + 8 * hA);
                mma_f16(oacc[8], aP, w00, w01);
            }
        }
    }

    // epilogue: write partial O and l (no smem, no barrier needed)
    const size_t r0 = (size_t)split * NTOK + row0 + wr0 + g;
    const size_t r1 = r0 + 8;
#pragma unroll
    for (int n = 0; n < 8; n++) {
        int col = 8 * n + 2 * t4;
        *(float2*)(g_po + r0 * DDIM + col) = make_float2(oacc[n][0], oacc[n][1]);
        *(float2*)(g_po + r1 * DDIM + col) = make_float2(oacc[n][2], oacc[n][3]);
    }
    if (t4 == 0) {
        g_pl[r0] = oacc[8][0];
        g_pl[r1] = oacc[8][2];
    }
}

// ---------------------------------------------------------------------------
// Kernel 3: merge split-KV partials, write 16x-tiled output
// ---------------------------------------------------------------------------
__global__ __launch_bounds__(256, 1) void merge_kernel(float* __restrict__ out)
{
    int g   = blockIdx.x * 256 + threadIdx.x;
    int row = g >> 4;
    int cg  = (g & 15) * 4;
    float l   = g_pl[row] + g_pl[NTOK + row];
    float inv = 1.f / l;
    float4 a = *(const float4*)(g_po + (size_t)row * DDIM + cg);
    float4 b = *(const float4*)(g_po + (size_t)(NTOK + row) * DDIM + cg);
    float4 y = make_float4((a.x + b.x) * inv, (a.y + b.y) * inv,
                           (a.z + b.z) * inv, (a.w + b.w) * inv);
    float* op = out + (size_t)row * 1024 + cg;
#pragma unroll
    for (int h = 0; h < 16; h++) *(float4*)(op + h * 64) = y;
}

// ---------------------------------------------------------------------------
extern "C" void kernel_launch(void* const* d_in, const int* in_sizes, int n_in,
                              void* d_out, int out_size)
{
    const float* x  = (const float*)d_in[0];
    const float* Wq = (const float*)d_in[1];
    const float* bq = (const float*)d_in[2];
    const float* Wk = (const float*)d_in[3];
    const float* bk = (const float*)d_in[4];
    const float* Wv = (const float*)d_in[5];
    const float* bv = (const float*)d_in[6];
    float* out = (float*)d_out;

    wconv<<<96, 256>>>(Wq, Wk, Wv);

    cudaFuncSetAttribute(qkv_mma, cudaFuncAttributeMaxDynamicSharedMemorySize,
                         QKV_SMEM_BYTES);
    qkv_mma<<<128, 256, QKV_SMEM_BYTES>>>(x, bq, bk, bv);

    cudaFuncSetAttribute(flash_mma, cudaFuncAttributeMaxDynamicSharedMemorySize,
                         FLASH_SMEM_BYTES);
    flash_mma<<<dim3(64, 2), 256, FLASH_SMEM_BYTES>>>();

    merge_kernel<<<512, 256>>>(out);
}

// round 11
// speedup vs baseline: 2.7658x; 1.0728x over previous
#include <cuda_runtime.h>
#include <cuda_fp16.h>
#include <cstdint>

#define NTOK 8192
#define CDIM 1024
#define DDIM 64
#define BM 256
#define BN 128
#define SPLITS 4
#define KEYS_PER_SPLIT (NTOK / SPLITS)
#define CHUNKS (KEYS_PER_SPLIT / BN)

// q pre-scale: log2(e)/32 so S accumulators are base-2 exponents
#define QSCALE 0.045084220027780106f

// scratch (allocation-free)
__device__ __half g_qh[NTOK * DDIM];
__device__ __half g_kh[NTOK * DDIM];
__device__ __half g_vT[DDIM * NTOK];           // V^T, half [d][tok]
__device__ __half g_wh[192 * CDIM];            // [Wq|Wk|Wv] in half
__device__ float  g_po[SPLITS * NTOK * DDIM];  // partial O
__device__ float  g_pl[SPLITS * NTOK];         // partial l

// m16n8k16 fp16 HMMA, fp32 accumulate
__device__ __forceinline__ void mma_f16(float* c, const uint32_t* a,
                                        uint32_t b0, uint32_t b1) {
    asm volatile(
        "mma.sync.aligned.m16n8k16.row.col.f32.f16.f16.f32 "
        "{%0,%1,%2,%3}, {%4,%5,%6,%7}, {%8,%9}, {%0,%1,%2,%3};"
        : "+f"(c[0]), "+f"(c[1]), "+f"(c[2]), "+f"(c[3])
        : "r"(a[0]), "r"(a[1]), "r"(a[2]), "r"(a[3]), "r"(b0), "r"(b1));
}
__device__ __forceinline__ void ldsm_x4(uint32_t& r0, uint32_t& r1,
                                        uint32_t& r2, uint32_t& r3,
                                        const __half* p) {
    uint32_t a = (uint32_t)__cvta_generic_to_shared(p);
    asm volatile("ldmatrix.sync.aligned.m8n8.x4.shared.b16 {%0,%1,%2,%3}, [%4];"
                 : "=r"(r0), "=r"(r1), "=r"(r2), "=r"(r3) : "r"(a));
}
__device__ __forceinline__ void cp_async16(const void* smem_ptr, const void* gptr) {
    uint32_t sa = (uint32_t)__cvta_generic_to_shared(smem_ptr);
    asm volatile("cp.async.cg.shared.global [%0], [%1], 16;"
                 :: "r"(sa), "l"(gptr) : "memory");
}
#define CP_COMMIT() asm volatile("cp.async.commit_group;" ::: "memory")
#define CP_WAIT0()  asm volatile("cp.async.wait_group 0;" ::: "memory")

__device__ __forceinline__ uint32_t h2(float a, float b) {
    __half2 h = __floats2half2_rn(a, b);
    return *(uint32_t*)&h;
}
__device__ __forceinline__ uint32_t ex2_f16x2(uint32_t a) {
    uint32_t d;
    asm("ex2.approx.f16x2 %0, %1;" : "=r"(d) : "r"(a));
    return d;
}

// ---------------------------------------------------------------------------
// Kernel 0: one-time W -> half conversion ([Wq|Wk|Wv] rows, 192x1024)
// ---------------------------------------------------------------------------
__global__ __launch_bounds__(256, 1) void wconv(
    const float* __restrict__ Wq, const float* __restrict__ Wk,
    const float* __restrict__ Wv)
{
    int idx  = blockIdx.x * 256 + threadIdx.x;   // 0..24575
    int base = idx * 8;
    int row  = base >> 10;
    int col  = base & 1023;
    const float* W = (row < 64) ? Wq + (size_t)row * CDIM
                   : (row < 128) ? Wk + (size_t)(row - 64) * CDIM
                                 : Wv + (size_t)(row - 128) * CDIM;
    float4 a = *(const float4*)(W + col);
    float4 b = *(const float4*)(W + col + 4);
    uint4 o;
    o.x = h2(a.x, a.y); o.y = h2(a.z, a.w);
    o.z = h2(b.x, b.y); o.w = h2(b.z, b.w);
    *(uint4*)(g_wh + base) = o;
}

// ---------------------------------------------------------------------------
// Kernel 1: QKV projection, fp16 MMA, ONE barrier per 64-k chunk.
// grid 128 (64 rows), 256 thr = 4 m-warps x 2 n-halves (96 cols).
// dyn smem (halfs): xh[2][64*72] | ws[2][192*72]
// ---------------------------------------------------------------------------
#define XP 72
#define XHB 4608
#define WSB 13824
#define QKV_SMEM_BYTES ((2 * XHB + 2 * WSB) * 2)

__global__ __launch_bounds__(256, 1) void qkv_mma(
    const float* __restrict__ x,
    const float* __restrict__ bq, const float* __restrict__ bk,
    const float* __restrict__ bv)
{
    extern __shared__ __half smq[];
    __half* xh = smq;
    __half* ws = smq + 2 * XHB;

    const int tid  = threadIdx.x;
    const int warp = tid >> 5;
    const int lane = tid & 31;
    const int r8   = lane & 7;
    const int hA   = (lane >> 3) & 1;
    const int hB   = lane >> 4;
    const int wm   = warp & 3;
    const int nh   = warp >> 2;
    const int row0 = blockIdx.x * 64;

    int xr[4], xc[4];
    const float* xptr[4];
#pragma unroll
    for (int i = 0; i < 4; i++) {
        int idx = i * 256 + tid;
        xr[i] = idx >> 4; xc[i] = (idx & 15) * 4;
        xptr[i] = x + (size_t)(row0 + xr[i]) * CDIM + xc[i];
    }
    int wr[6], wc8[6];
#pragma unroll
    for (int i = 0; i < 6; i++) {
        int idx = i * 256 + tid;
        wr[i] = idx >> 3; wc8[i] = (idx & 7) * 8;
    }

    // prologue: prefetch x chunk 0, issue W chunk 0
    float4 xreg[4];
#pragma unroll
    for (int i = 0; i < 4; i++) xreg[i] = *(const float4*)(xptr[i]);
#pragma unroll
    for (int i = 0; i < 6; i++)
        cp_async16(ws + wr[i] * XP + wc8[i], g_wh + (size_t)wr[i] * CDIM + wc8[i]);
    CP_COMMIT();

    float oacc[12][4];
#pragma unroll
    for (int n = 0; n < 12; n++)
#pragma unroll
        for (int j = 0; j < 4; j++) oacc[n][j] = 0.f;

    for (int kc = 0; kc < 16; kc++) {
        const int b = kc & 1;
        // store converted x into xh[b] (laggards read xh[b^1]; safe)
#pragma unroll
        for (int i = 0; i < 4; i++) {
            float4 v = xreg[i];
            uint2 hi;
            hi.x = h2(v.x, v.y);
            hi.y = h2(v.z, v.w);
            *(uint2*)(xh + b * XHB + xr[i] * XP + xc[i]) = hi;
        }
        CP_WAIT0();        // W chunk kc complete
        __syncthreads();   // the one barrier: xh[b]+ws[b] visible, buffers retired

        if (kc < 15) {
            // issue next W (everyone finished reading ws[b^1] in chunk kc-1)
#pragma unroll
            for (int i = 0; i < 6; i++)
                cp_async16(ws + (b ^ 1) * WSB + wr[i] * XP + wc8[i],
                           g_wh + (size_t)wr[i] * CDIM + (kc + 1) * 64 + wc8[i]);
            CP_COMMIT();
            // prefetch next x chunk (overlaps MMA)
#pragma unroll
            for (int i = 0; i < 4; i++)
                xreg[i] = *(const float4*)(xptr[i] + (kc + 1) * 64);
        }

        const __half* xb = xh + b * XHB;
        const __half* wb = ws + b * WSB;
#pragma unroll
        for (int kk = 0; kk < 4; kk++) {
            uint32_t ah[4];
            ldsm_x4(ah[0], ah[1], ah[2], ah[3],
                    xb + (wm * 16 + 8 * hA + r8) * XP + 16 * kk + 8 * hB);
#pragma unroll
            for (int np = 0; np < 6; np++) {
                uint32_t b00, b01, b10, b11;
                ldsm_x4(b00, b01, b10, b11,
                        wb + (nh * 96 + 16 * np + 8 * hB + r8) * XP
                           + 16 * kk + 8 * hA);
                mma_f16(oacc[2 * np],     ah, b00, b01);
                mma_f16(oacc[2 * np + 1], ah, b10, b11);
            }
        }
    }

    // epilogue: bias, half outputs
    const int g  = lane >> 2;
    const int t4 = lane & 3;
    const int r0 = row0 + wm * 16 + g;
#pragma unroll
    for (int n = 0; n < 12; n++) {
        int cb = nh * 96 + 8 * n + 2 * t4;
        if (cb < 64) {
            float2 bias = *(const float2*)(bq + cb);
            *(uint32_t*)(g_qh + (size_t)r0 * DDIM + cb) =
                h2((oacc[n][0] + bias.x) * QSCALE, (oacc[n][1] + bias.y) * QSCALE);
            *(uint32_t*)(g_qh + (size_t)(r0 + 8) * DDIM + cb) =
                h2((oacc[n][2] + bias.x) * QSCALE, (oacc[n][3] + bias.y) * QSCALE);
        } else if (cb < 128) {
            int col = cb - 64;
            float2 bias = *(const float2*)(bk + col);
            *(uint32_t*)(g_kh + (size_t)r0 * DDIM + col) =
                h2(oacc[n][0] + bias.x, oacc[n][1] + bias.y);
            *(uint32_t*)(g_kh + (size_t)(r0 + 8) * DDIM + col) =
                h2(oacc[n][2] + bias.x, oacc[n][3] + bias.y);
        } else {
            int col = cb - 128;
            float bx = bv[col], by = bv[col + 1];
            g_vT[(size_t)col * NTOK + r0]           = __float2half_rn(oacc[n][0] + bx);
            g_vT[(size_t)(col + 1) * NTOK + r0]     = __float2half_rn(oacc[n][1] + by);
            g_vT[(size_t)col * NTOK + r0 + 8]       = __float2half_rn(oacc[n][2] + bx);
            g_vT[(size_t)(col + 1) * NTOK + r0 + 8] = __float2half_rn(oacc[n][3] + by);
        }
    }
}

// ---------------------------------------------------------------------------
// Kernel 2: fp16 flash attention, register-resident P, l-via-ones-MMA.
// BM=256, SPLITS=4, grid (32,4)=128 CTAs, 512 thr = 16 m-warps.
// Double-buffered cp.async, sync-then-issue (one barrier + one wait / chunk).
// smem (halfs): K[2][128*72] | V[2][80*136] (V rows 64..79: ones + zeros)
// ---------------------------------------------------------------------------
#define KP 72
#define VP 136
#define KBUF (128 * KP)
#define VBUF (80 * VP)
#define HVBASE (2 * KBUF)
#define HEND (HVBASE + 2 * VBUF)
#define FLASH_SMEM_BYTES (HEND * 2)

__global__ __launch_bounds__(512, 1) void flash_mma()
{
    extern __shared__ __half smh[];

    const int tid   = threadIdx.x;
    const int warp  = tid >> 5;
    const int lane  = tid & 31;
    const int r8    = lane & 7;
    const int hA    = (lane >> 3) & 1;
    const int hB    = lane >> 4;
    const int g     = lane >> 2;
    const int t4    = lane & 3;
    const int wr0   = warp * 16;
    const int row0  = blockIdx.x * BM;
    const int split = blockIdx.y;
    const int key0  = split * KEYS_PER_SPLIT;

    // init ones/zero rows (64..79) of both V buffers
    for (int i = tid; i < 2 * 16 * VP; i += 512) {
        int b  = i / (16 * VP);
        int rr = (i % (16 * VP)) / VP;
        int cc = i % VP;
        smh[HVBASE + b * VBUF + (64 + rr) * VP + cc] =
            (rr == 0) ? __float2half(1.f) : __float2half(0.f);
    }

    // Q A-fragments from global (pre-scaled by QSCALE)
    uint32_t aQ[4][4];
    {
        const __half* q0 = g_qh + (size_t)(row0 + wr0 + g) * DDIM;
        const __half* q1 = q0 + 8 * DDIM;
#pragma unroll
        for (int kk = 0; kk < 4; kk++) {
            int c0 = 16 * kk + 2 * t4;
            aQ[kk][0] = *(const uint32_t*)(q0 + c0);
            aQ[kk][1] = *(const uint32_t*)(q1 + c0);
            aQ[kk][2] = *(const uint32_t*)(q0 + c0 + 8);
            aQ[kk][3] = *(const uint32_t*)(q1 + c0 + 8);
        }
    }

    // staging coordinates: 2 K + 2 V cp.async16 per thread per chunk
    int kr[2], kc8[2], vr[2], vc8[2];
#pragma unroll
    for (int i = 0; i < 2; i++) {
        int idx = i * 512 + tid;
        kr[i] = idx >> 3;  kc8[i] = (idx & 7) * 8;
        vr[i] = idx >> 4;  vc8[i] = (idx & 15) * 8;
    }

    // prologue: issue chunk 0 into buffer 0
#pragma unroll
    for (int i = 0; i < 2; i++) {
        cp_async16(smh + kr[i] * KP + kc8[i],
                   g_kh + (size_t)(key0 + kr[i]) * DDIM + kc8[i]);
        cp_async16(smh + HVBASE + vr[i] * VP + vc8[i],
                   g_vT + (size_t)vr[i] * NTOK + key0 + vc8[i]);
    }
    CP_COMMIT();

    float oacc[9][4];
#pragma unroll
    for (int n = 0; n < 9; n++)
#pragma unroll
        for (int j = 0; j < 4; j++) oacc[n][j] = 0.f;

    for (int ch = 0; ch < CHUNKS; ch++) {
        CP_WAIT0();        // chunk ch complete
        __syncthreads();   // visibility + everyone done with the other buffer

        // issue next chunk into the other buffer (safe after the barrier)
        if (ch + 1 < CHUNKS) {
            const size_t nb = (size_t)(key0 + (ch + 1) * BN);
            __half* kb = smh + ((ch + 1) & 1) * KBUF;
            __half* vb = smh + HVBASE + ((ch + 1) & 1) * VBUF;
#pragma unroll
            for (int i = 0; i < 2; i++) {
                cp_async16(kb + kr[i] * KP + kc8[i],
                           g_kh + (nb + kr[i]) * DDIM + kc8[i]);
                cp_async16(vb + vr[i] * VP + vc8[i],
                           g_vT + (size_t)vr[i] * NTOK + nb + vc8[i]);
            }
            CP_COMMIT();
        }

        const __half* Ks = smh + (ch & 1) * KBUF;
        const __half* Vs = smh + HVBASE + (ch & 1) * VBUF;

        // fused S -> exp -> PV per 16-key group
#pragma unroll
        for (int j2 = 0; j2 < 8; j2++) {
            float s0[4] = {0.f, 0.f, 0.f, 0.f};
            float s1[4] = {0.f, 0.f, 0.f, 0.f};
#pragma unroll
            for (int kk = 0; kk < 4; kk++) {
                uint32_t b00, b01, b10, b11;
                ldsm_x4(b00, b01, b10, b11,
                        Ks + (16 * j2 + 8 * hB + r8) * KP + 16 * kk + 8 * hA);
                mma_f16(s0, aQ[kk], b00, b01);
                mma_f16(s1, aQ[kk], b10, b11);
            }
            uint32_t aP[4];
            aP[0] = ex2_f16x2(h2(s0[0], s0[1]));
            aP[1] = ex2_f16x2(h2(s0[2], s0[3]));
            aP[2] = ex2_f16x2(h2(s1[0], s1[1]));
            aP[3] = ex2_f16x2(h2(s1[2], s1[3]));
#pragma unroll
            for (int np = 0; np < 4; np++) {
                uint32_t v00, v01, v10, v11;
                ldsm_x4(v00, v01, v10, v11,
                        Vs + (16 * np + 8 * hB + r8) * VP + 16 * j2 + 8 * hA);
                mma_f16(oacc[2 * np],     aP, v00, v01);
                mma_f16(oacc[2 * np + 1], aP, v10, v11);
            }
            {
                uint32_t w00, w01, w10, w11;
                ldsm_x4(w00, w01, w10, w11,
                        Vs + (64 + 8 * hB + r8) * VP + 16 * j2 + 8 * hA);
                mma_f16(oacc[8], aP, w00, w01);
            }
        }
    }

    // epilogue: write partial O and l
    const size_t r0 = (size_t)split * NTOK + row0 + wr0 + g;
    const size_t r1 = r0 + 8;
#pragma unroll
    for (int n = 0; n < 8; n++) {
        int col = 8 * n + 2 * t4;
        *(float2*)(g_po + r0 * DDIM + col) = make_float2(oacc[n][0], oacc[n][1]);
        *(float2*)(g_po + r1 * DDIM + col) = make_float2(oacc[n][2], oacc[n][3]);
    }
    if (t4 == 0) {
        g_pl[r0] = oacc[8][0];
        g_pl[r1] = oacc[8][2];
    }
}

// ---------------------------------------------------------------------------
// Kernel 3: merge 4 split-KV partials, write 16x-tiled output
// ---------------------------------------------------------------------------
__global__ __launch_bounds__(256, 1) void merge_kernel(float* __restrict__ out)
{
    int g   = blockIdx.x * 256 + threadIdx.x;
    int row = g >> 4;
    int cg  = (g & 15) * 4;
    float l = g_pl[row] + g_pl[NTOK + row]
            + g_pl[2 * NTOK + row] + g_pl[3 * NTOK + row];
    float inv = 1.f / l;
    float4 a = *(const float4*)(g_po + (size_t)row * DDIM + cg);
    float4 b = *(const float4*)(g_po + ((size_t)NTOK + row) * DDIM + cg);
    float4 c = *(const float4*)(g_po + ((size_t)2 * NTOK + row) * DDIM + cg);
    float4 d = *(const float4*)(g_po + ((size_t)3 * NTOK + row) * DDIM + cg);
    float4 y = make_float4((a.x + b.x + c.x + d.x) * inv,
                           (a.y + b.y + c.y + d.y) * inv,
                           (a.z + b.z + c.z + d.z) * inv,
                           (a.w + b.w + c.w + d.w) * inv);
    float* op = out + (size_t)row * 1024 + cg;
#pragma unroll
    for (int h = 0; h < 16; h++) *(float4*)(op + h * 64) = y;
}

// ---------------------------------------------------------------------------
extern "C" void kernel_launch(void* const* d_in, const int* in_sizes, int n_in,
                              void* d_out, int out_size)
{
    const float* x  = (const float*)d_in[0];
    const float* Wq = (const float*)d_in[1];
    const float* bq = (const float*)d_in[2];
    const float* Wk = (const float*)d_in[3];
    const float* bk = (const float*)d_in[4];
    const float* Wv = (const float*)d_in[5];
    const float* bv = (const float*)d_in[6];
    float* out = (float*)d_out;

    wconv<<<96, 256>>>(Wq, Wk, Wv);

    cudaFuncSetAttribute(qkv_mma, cudaFuncAttributeMaxDynamicSharedMemorySize,
                         QKV_SMEM_BYTES);
    qkv_mma<<<128, 256, QKV_SMEM_BYTES>>>(x, bq, bk, bv);

    cudaFuncSetAttribute(flash_mma, cudaFuncAttributeMaxDynamicSharedMemorySize,
                         FLASH_SMEM_BYTES);
    flash_mma<<<dim3(32, 4), 512, FLASH_SMEM_BYTES>>>();

    merge_kernel<<<512, 256>>>(out);
}

// round 12
// speedup vs baseline: 2.8439x; 1.0283x over previous
#include <cuda_runtime.h>
#include <cuda_fp16.h>
#include <cstdint>

#define NTOK 8192
#define CDIM 1024
#define DDIM 64
#define BM 256
#define BN 128
#define SPLITS 4
#define KEYS_PER_SPLIT (NTOK / SPLITS)
#define CHUNKS (KEYS_PER_SPLIT / BN)

// q pre-scale: log2(e)/32 so S accumulators are base-2 exponents
#define QSCALE 0.045084220027780106f

// scratch (allocation-free)
__device__ __half g_qh[NTOK * DDIM];
__device__ __half g_kh[NTOK * DDIM];
__device__ __half g_vT[DDIM * NTOK];           // V^T, half [d][tok]
__device__ __half g_wh[192 * CDIM];            // [Wq|Wk|Wv] in half
__device__ float  g_po[SPLITS * NTOK * DDIM];  // partial O
__device__ float  g_pl[SPLITS * NTOK];         // partial l

// m16n8k16 fp16 HMMA, fp32 accumulate
__device__ __forceinline__ void mma_f16(float* c, const uint32_t* a,
                                        uint32_t b0, uint32_t b1) {
    asm volatile(
        "mma.sync.aligned.m16n8k16.row.col.f32.f16.f16.f32 "
        "{%0,%1,%2,%3}, {%4,%5,%6,%7}, {%8,%9}, {%0,%1,%2,%3};"
        : "+f"(c[0]), "+f"(c[1]), "+f"(c[2]), "+f"(c[3])
        : "r"(a[0]), "r"(a[1]), "r"(a[2]), "r"(a[3]), "r"(b0), "r"(b1));
}
__device__ __forceinline__ void ldsm_x4(uint32_t& r0, uint32_t& r1,
                                        uint32_t& r2, uint32_t& r3,
                                        const __half* p) {
    uint32_t a = (uint32_t)__cvta_generic_to_shared(p);
    asm volatile("ldmatrix.sync.aligned.m8n8.x4.shared.b16 {%0,%1,%2,%3}, [%4];"
                 : "=r"(r0), "=r"(r1), "=r"(r2), "=r"(r3) : "r"(a));
}
__device__ __forceinline__ void cp_async16(const void* smem_ptr, const void* gptr) {
    uint32_t sa = (uint32_t)__cvta_generic_to_shared(smem_ptr);
    asm volatile("cp.async.cg.shared.global [%0], [%1], 16;"
                 :: "r"(sa), "l"(gptr) : "memory");
}
#define CP_COMMIT() asm volatile("cp.async.commit_group;" ::: "memory")
#define CP_WAIT0()  asm volatile("cp.async.wait_group 0;" ::: "memory")

__device__ __forceinline__ uint32_t h2(float a, float b) {
    __half2 h = __floats2half2_rn(a, b);
    return *(uint32_t*)&h;
}
__device__ __forceinline__ uint32_t ex2_f16x2(uint32_t a) {
    uint32_t d;
    asm("ex2.approx.f16x2 %0, %1;" : "=r"(d) : "r"(a));
    return d;
}

// ---------------------------------------------------------------------------
// Kernel 0: one-time W -> half conversion ([Wq|Wk|Wv] rows, 192x1024)
// ---------------------------------------------------------------------------
__global__ __launch_bounds__(256, 1) void wconv(
    const float* __restrict__ Wq, const float* __restrict__ Wk,
    const float* __restrict__ Wv)
{
    int idx  = blockIdx.x * 256 + threadIdx.x;   // 0..24575
    int base = idx * 8;
    int row  = base >> 10;
    int col  = base & 1023;
    const float* W = (row < 64) ? Wq + (size_t)row * CDIM
                   : (row < 128) ? Wk + (size_t)(row - 64) * CDIM
                                 : Wv + (size_t)(row - 128) * CDIM;
    float4 a = *(const float4*)(W + col);
    float4 b = *(const float4*)(W + col + 4);
    uint4 o;
    o.x = h2(a.x, a.y); o.y = h2(a.z, a.w);
    o.z = h2(b.x, b.y); o.w = h2(b.z, b.w);
    *(uint4*)(g_wh + base) = o;
}

// ---------------------------------------------------------------------------
// Kernel 1: QKV projection, fp16 MMA, ONE barrier per 64-k chunk.
// grid 128 (64 rows), 256 thr = 4 m-warps x 2 n-halves (96 cols).
// dyn smem (halfs): xh[2][64*72] | ws[2][192*72]
// ---------------------------------------------------------------------------
#define XP 72
#define XHB 4608
#define WSB 13824
#define QKV_SMEM_BYTES ((2 * XHB + 2 * WSB) * 2)

__global__ __launch_bounds__(256, 1) void qkv_mma(
    const float* __restrict__ x,
    const float* __restrict__ bq, const float* __restrict__ bk,
    const float* __restrict__ bv)
{
    extern __shared__ __half smq[];
    __half* xh = smq;
    __half* ws = smq + 2 * XHB;

    const int tid  = threadIdx.x;
    const int warp = tid >> 5;
    const int lane = tid & 31;
    const int r8   = lane & 7;
    const int hA   = (lane >> 3) & 1;
    const int hB   = lane >> 4;
    const int wm   = warp & 3;
    const int nh   = warp >> 2;
    const int row0 = blockIdx.x * 64;

    int xr[4], xc[4];
    const float* xptr[4];
#pragma unroll
    for (int i = 0; i < 4; i++) {
        int idx = i * 256 + tid;
        xr[i] = idx >> 4; xc[i] = (idx & 15) * 4;
        xptr[i] = x + (size_t)(row0 + xr[i]) * CDIM + xc[i];
    }
    int wr[6], wc8[6];
#pragma unroll
    for (int i = 0; i < 6; i++) {
        int idx = i * 256 + tid;
        wr[i] = idx >> 3; wc8[i] = (idx & 7) * 8;
    }

    // prologue: prefetch x chunk 0, issue W chunk 0
    float4 xreg[4];
#pragma unroll
    for (int i = 0; i < 4; i++) xreg[i] = *(const float4*)(xptr[i]);
#pragma unroll
    for (int i = 0; i < 6; i++)
        cp_async16(ws + wr[i] * XP + wc8[i], g_wh + (size_t)wr[i] * CDIM + wc8[i]);
    CP_COMMIT();

    float oacc[12][4];
#pragma unroll
    for (int n = 0; n < 12; n++)
#pragma unroll
        for (int j = 0; j < 4; j++) oacc[n][j] = 0.f;

    for (int kc = 0; kc < 16; kc++) {
        const int b = kc & 1;
#pragma unroll
        for (int i = 0; i < 4; i++) {
            float4 v = xreg[i];
            uint2 hi;
            hi.x = h2(v.x, v.y);
            hi.y = h2(v.z, v.w);
            *(uint2*)(xh + b * XHB + xr[i] * XP + xc[i]) = hi;
        }
        CP_WAIT0();
        __syncthreads();

        if (kc < 15) {
#pragma unroll
            for (int i = 0; i < 6; i++)
                cp_async16(ws + (b ^ 1) * WSB + wr[i] * XP + wc8[i],
                           g_wh + (size_t)wr[i] * CDIM + (kc + 1) * 64 + wc8[i]);
            CP_COMMIT();
#pragma unroll
            for (int i = 0; i < 4; i++)
                xreg[i] = *(const float4*)(xptr[i] + (kc + 1) * 64);
        }

        const __half* xb = xh + b * XHB;
        const __half* wb = ws + b * WSB;
#pragma unroll
        for (int kk = 0; kk < 4; kk++) {
            uint32_t ah[4];
            ldsm_x4(ah[0], ah[1], ah[2], ah[3],
                    xb + (wm * 16 + 8 * hA + r8) * XP + 16 * kk + 8 * hB);
#pragma unroll
            for (int np = 0; np < 6; np++) {
                uint32_t b00, b01, b10, b11;
                ldsm_x4(b00, b01, b10, b11,
                        wb + (nh * 96 + 16 * np + 8 * hB + r8) * XP
                           + 16 * kk + 8 * hA);
                mma_f16(oacc[2 * np],     ah, b00, b01);
                mma_f16(oacc[2 * np + 1], ah, b10, b11);
            }
        }
    }

    // epilogue: bias, half outputs
    const int g  = lane >> 2;
    const int t4 = lane & 3;
    const int r0 = row0 + wm * 16 + g;
#pragma unroll
    for (int n = 0; n < 12; n++) {
        int cb = nh * 96 + 8 * n + 2 * t4;
        if (cb < 64) {
            float2 bias = *(const float2*)(bq + cb);
            *(uint32_t*)(g_qh + (size_t)r0 * DDIM + cb) =
                h2((oacc[n][0] + bias.x) * QSCALE, (oacc[n][1] + bias.y) * QSCALE);
            *(uint32_t*)(g_qh + (size_t)(r0 + 8) * DDIM + cb) =
                h2((oacc[n][2] + bias.x) * QSCALE, (oacc[n][3] + bias.y) * QSCALE);
        } else if (cb < 128) {
            int col = cb - 64;
            float2 bias = *(const float2*)(bk + col);
            *(uint32_t*)(g_kh + (size_t)r0 * DDIM + col) =
                h2(oacc[n][0] + bias.x, oacc[n][1] + bias.y);
            *(uint32_t*)(g_kh + (size_t)(r0 + 8) * DDIM + col) =
                h2(oacc[n][2] + bias.x, oacc[n][3] + bias.y);
        } else {
            int col = cb - 128;
            float bx = bv[col], by = bv[col + 1];
            g_vT[(size_t)col * NTOK + r0]           = __float2half_rn(oacc[n][0] + bx);
            g_vT[(size_t)(col + 1) * NTOK + r0]     = __float2half_rn(oacc[n][1] + by);
            g_vT[(size_t)col * NTOK + r0 + 8]       = __float2half_rn(oacc[n][2] + bx);
            g_vT[(size_t)(col + 1) * NTOK + r0 + 8] = __float2half_rn(oacc[n][3] + by);
        }
    }
}

// ---------------------------------------------------------------------------
// Kernel 2: fp16 flash attention. 8 warps x 32 rows (2 m16 tiles per warp,
// every K/V fragment feeds 4 MMAs). Register-resident P, l-via-ones-MMA.
// BM=256, SPLITS=4, grid (32,4)=128 CTAs, 256 thr.
// smem (halfs): K[2][128*72] | V[2][80*136] (V rows 64..79: ones + zeros)
// ---------------------------------------------------------------------------
#define KP 72
#define VP 136
#define KBUF (128 * KP)
#define VBUF (80 * VP)
#define HVBASE (2 * KBUF)
#define HEND (HVBASE + 2 * VBUF)
#define FLASH_SMEM_BYTES (HEND * 2)

__global__ __launch_bounds__(256, 1) void flash_mma()
{
    extern __shared__ __half smh[];

    const int tid   = threadIdx.x;
    const int warp  = tid >> 5;
    const int lane  = tid & 31;
    const int r8    = lane & 7;
    const int hA    = (lane >> 3) & 1;
    const int hB    = lane >> 4;
    const int g     = lane >> 2;
    const int t4    = lane & 3;
    const int wr0   = warp * 32;           // 32 rows per warp
    const int row0  = blockIdx.x * BM;
    const int split = blockIdx.y;
    const int key0  = split * KEYS_PER_SPLIT;

    // init ones/zero rows (64..79) of both V buffers
    for (int i = tid; i < 2 * 16 * VP; i += 256) {
        int b  = i / (16 * VP);
        int rr = (i % (16 * VP)) / VP;
        int cc = i % VP;
        smh[HVBASE + b * VBUF + (64 + rr) * VP + cc] =
            (rr == 0) ? __float2half(1.f) : __float2half(0.f);
    }

    // Q A-fragments for 2 m-tiles (pre-scaled by QSCALE)
    uint32_t aQ[2][4][4];
#pragma unroll
    for (int m = 0; m < 2; m++) {
        const __half* q0 = g_qh + (size_t)(row0 + wr0 + m * 16 + g) * DDIM;
        const __half* q1 = q0 + 8 * DDIM;
#pragma unroll
        for (int kk = 0; kk < 4; kk++) {
            int c0 = 16 * kk + 2 * t4;
            aQ[m][kk][0] = *(const uint32_t*)(q0 + c0);
            aQ[m][kk][1] = *(const uint32_t*)(q1 + c0);
            aQ[m][kk][2] = *(const uint32_t*)(q0 + c0 + 8);
            aQ[m][kk][3] = *(const uint32_t*)(q1 + c0 + 8);
        }
    }

    // staging coordinates: 4 K + 4 V cp.async16 per thread per chunk
    int kr[4], kc8[4], vr[4], vc8[4];
#pragma unroll
    for (int i = 0; i < 4; i++) {
        int idx = i * 256 + tid;
        kr[i] = idx >> 3;  kc8[i] = (idx & 7) * 8;
        vr[i] = idx >> 4;  vc8[i] = (idx & 15) * 8;
    }

    // prologue: issue chunk 0 into buffer 0
#pragma unroll
    for (int i = 0; i < 4; i++) {
        cp_async16(smh + kr[i] * KP + kc8[i],
                   g_kh + (size_t)(key0 + kr[i]) * DDIM + kc8[i]);
        cp_async16(smh + HVBASE + vr[i] * VP + vc8[i],
                   g_vT + (size_t)vr[i] * NTOK + key0 + vc8[i]);
    }
    CP_COMMIT();

    float oacc[2][9][4];
#pragma unroll
    for (int m = 0; m < 2; m++)
#pragma unroll
        for (int n = 0; n < 9; n++)
#pragma unroll
            for (int j = 0; j < 4; j++) oacc[m][n][j] = 0.f;

    for (int ch = 0; ch < CHUNKS; ch++) {
        CP_WAIT0();        // chunk ch complete
        __syncthreads();   // visibility + everyone done with the other buffer

        if (ch + 1 < CHUNKS) {
            const size_t nb = (size_t)(key0 + (ch + 1) * BN);
            __half* kb = smh + ((ch + 1) & 1) * KBUF;
            __half* vb = smh + HVBASE + ((ch + 1) & 1) * VBUF;
#pragma unroll
            for (int i = 0; i < 4; i++) {
                cp_async16(kb + kr[i] * KP + kc8[i],
                           g_kh + (nb + kr[i]) * DDIM + kc8[i]);
                cp_async16(vb + vr[i] * VP + vc8[i],
                           g_vT + (size_t)vr[i] * NTOK + nb + vc8[i]);
            }
            CP_COMMIT();
        }

        const __half* Ks = smh + (ch & 1) * KBUF;
        const __half* Vs = smh + HVBASE + (ch & 1) * VBUF;

        // fused S -> exp -> PV per 16-key group; K/V fragments reused x2
#pragma unroll
        for (int j2 = 0; j2 < 8; j2++) {
            float s[2][2][4];
#pragma unroll
            for (int m = 0; m < 2; m++)
#pragma unroll
                for (int q = 0; q < 2; q++)
#pragma unroll
                    for (int j = 0; j < 4; j++) s[m][q][j] = 0.f;
#pragma unroll
            for (int kk = 0; kk < 4; kk++) {
                uint32_t b00, b01, b10, b11;
                ldsm_x4(b00, b01, b10, b11,
                        Ks + (16 * j2 + 8 * hB + r8) * KP + 16 * kk + 8 * hA);
                mma_f16(s[0][0], aQ[0][kk], b00, b01);
                mma_f16(s[0][1], aQ[0][kk], b10, b11);
                mma_f16(s[1][0], aQ[1][kk], b00, b01);
                mma_f16(s[1][1], aQ[1][kk], b10, b11);
            }
            uint32_t aP[2][4];
#pragma unroll
            for (int m = 0; m < 2; m++) {
                aP[m][0] = ex2_f16x2(h2(s[m][0][0], s[m][0][1]));
                aP[m][1] = ex2_f16x2(h2(s[m][0][2], s[m][0][3]));
                aP[m][2] = ex2_f16x2(h2(s[m][1][0], s[m][1][1]));
                aP[m][3] = ex2_f16x2(h2(s[m][1][2], s[m][1][3]));
            }
#pragma unroll
            for (int np = 0; np < 4; np++) {
                uint32_t v00, v01, v10, v11;
                ldsm_x4(v00, v01, v10, v11,
                        Vs + (16 * np + 8 * hB + r8) * VP + 16 * j2 + 8 * hA);
                mma_f16(oacc[0][2 * np],     aP[0], v00, v01);
                mma_f16(oacc[0][2 * np + 1], aP[0], v10, v11);
                mma_f16(oacc[1][2 * np],     aP[1], v00, v01);
                mma_f16(oacc[1][2 * np + 1], aP[1], v10, v11);
            }
            {
                uint32_t w00, w01, w10, w11;
                ldsm_x4(w00, w01, w10, w11,
                        Vs + (64 + 8 * hB + r8) * VP + 16 * j2 + 8 * hA);
                mma_f16(oacc[0][8], aP[0], w00, w01);
                mma_f16(oacc[1][8], aP[1], w00, w01);
            }
        }
    }

    // epilogue: write partial O and l for both m-tiles
#pragma unroll
    for (int m = 0; m < 2; m++) {
        const size_t r0 = (size_t)split * NTOK + row0 + wr0 + m * 16 + g;
        const size_t r1 = r0 + 8;
#pragma unroll
        for (int n = 0; n < 8; n++) {
            int col = 8 * n + 2 * t4;
            *(float2*)(g_po + r0 * DDIM + col) =
                make_float2(oacc[m][n][0], oacc[m][n][1]);
            *(float2*)(g_po + r1 * DDIM + col) =
                make_float2(oacc[m][n][2], oacc[m][n][3]);
        }
        if (t4 == 0) {
            g_pl[r0] = oacc[m][8][0];
            g_pl[r1] = oacc[m][8][2];
        }
    }
}

// ---------------------------------------------------------------------------
// Kernel 3: merge 4 split-KV partials, write 16x-tiled output
// ---------------------------------------------------------------------------
__global__ __launch_bounds__(256, 1) void merge_kernel(float* __restrict__ out)
{
    int g   = blockIdx.x * 256 + threadIdx.x;
    int row = g >> 4;
    int cg  = (g & 15) * 4;
    float l = g_pl[row] + g_pl[NTOK + row]
            + g_pl[2 * NTOK + row] + g_pl[3 * NTOK + row];
    float inv = 1.f / l;
    float4 a = *(const float4*)(g_po + (size_t)row * DDIM + cg);
    float4 b = *(const float4*)(g_po + ((size_t)NTOK + row) * DDIM + cg);
    float4 c = *(const float4*)(g_po + ((size_t)2 * NTOK + row) * DDIM + cg);
    float4 d = *(const float4*)(g_po + ((size_t)3 * NTOK + row) * DDIM + cg);
    float4 y = make_float4((a.x + b.x + c.x + d.x) * inv,
                           (a.y + b.y + c.y + d.y) * inv,
                           (a.z + b.z + c.z + d.z) * inv,
                           (a.w + b.w + c.w + d.w) * inv);
    float* op = out + (size_t)row * 1024 + cg;
#pragma unroll
    for (int h = 0; h < 16; h++) *(float4*)(op + h * 64) = y;
}

// ---------------------------------------------------------------------------
extern "C" void kernel_launch(void* const* d_in, const int* in_sizes, int n_in,
                              void* d_out, int out_size)
{
    const float* x  = (const float*)d_in[0];
    const float* Wq = (const float*)d_in[1];
    const float* bq = (const float*)d_in[2];
    const float* Wk = (const float*)d_in[3];
    const float* bk = (const float*)d_in[4];
    const float* Wv = (const float*)d_in[5];
    const float* bv = (const float*)d_in[6];
    float* out = (float*)d_out;

    wconv<<<96, 256>>>(Wq, Wk, Wv);

    cudaFuncSetAttribute(qkv_mma, cudaFuncAttributeMaxDynamicSharedMemorySize,
                         QKV_SMEM_BYTES);
    qkv_mma<<<128, 256, QKV_SMEM_BYTES>>>(x, bq, bk, bv);

    cudaFuncSetAttribute(flash_mma, cudaFuncAttributeMaxDynamicSharedMemorySize,
                         FLASH_SMEM_BYTES);
    flash_mma<<<dim3(32, 4), 256, FLASH_SMEM_BYTES>>>();

    merge_kernel<<<512, 256>>>(out);
}